// round 3
// baseline (speedup 1.0000x reference)
#include <cuda_runtime.h>
#include <math.h>

// ---------------------------------------------------------------------------
// _NLBlock: B=8, T=1024, S=2048, C=1024, fp32
//   theta = x @ theta_w^T + theta_b                  [B,T,C]
//   phi   = lfb @ phi_w^T + phi_b                    [B,S,C]
//   gi    = lfb @ gi_w^T  + gi_b                     [B,S,C]
//   attn  = softmax( (theta @ phi^T) * sqrt(C) )     [B,T,S]
//   out   = relu(LN(attn @ gi)) @ fc_w^T + fc_b + x  [B,T,C]
// All GEMMs fp32 via packed fma.rn.f32x2 (2x the 3-reg FFMA rate on B300).
// ---------------------------------------------------------------------------

#define Bv 8
#define Tt 1024
#define Ss 2048
#define Cc 1024

// Scratch (device globals: allocation-free per harness rules)
__device__ float g_theta [Bv * Tt * Cc];   //  32 MB
__device__ float g_phi   [Bv * Ss * Cc];   //  64 MB
__device__ float g_gi    [Bv * Ss * Cc];   //  64 MB
__device__ float g_logits[Bv * Tt * Ss];   //  64 MB
__device__ float g_att   [Bv * Tt * Cc];   //  32 MB

// ---------------- packed f32x2 helpers (sm_100+) ----------------
__device__ __forceinline__ unsigned long long pk2(float lo, float hi) {
    unsigned long long r;
    asm("mov.b64 %0, {%1,%2};" : "=l"(r) : "f"(lo), "f"(hi));
    return r;
}
__device__ __forceinline__ void upk2(unsigned long long v, float& lo, float& hi) {
    asm("mov.b64 {%0,%1}, %2;" : "=f"(lo), "=f"(hi) : "l"(v));
}
__device__ __forceinline__ unsigned long long ffma2(unsigned long long a,
                                                    unsigned long long b,
                                                    unsigned long long c) {
    unsigned long long d;
    asm("fma.rn.f32x2 %0, %1, %2, %3;" : "=l"(d) : "l"(a), "l"(b), "l"(c));
    return d;
}

constexpr int BM = 128, BN = 128, BK = 16;

// ---------------------------------------------------------------------------
// NT GEMM: C[m,n] = alpha * sum_k A[m,k]*B[n,k] (+bias[n]) (+res[m,n])
// A row-major lda=K, B row-major ldb=K. Batched via blockIdx.z + strides.
// ---------------------------------------------------------------------------
__global__ void __launch_bounds__(256, 2) gemm_nt(
    const float* __restrict__ A, const float* __restrict__ B,
    const float* __restrict__ bias, const float* __restrict__ res,
    float* __restrict__ C,
    int N, int K, float alpha,
    size_t sA, size_t sB, size_t sC)
{
    __shared__ float As[BK][BM + 4];
    __shared__ float Bs[BK][BN + 4];
    const int tid = threadIdx.x;
    A += blockIdx.z * sA + (size_t)blockIdx.y * BM * K;
    B += blockIdx.z * sB + (size_t)blockIdx.x * BN * K;
    C += blockIdx.z * sC;
    if (res) res += blockIdx.z * sC;

    const int tr = tid >> 4, tc = tid & 15;
    unsigned long long acc[8][4];
#pragma unroll
    for (int i = 0; i < 8; i++)
#pragma unroll
        for (int j = 0; j < 4; j++) acc[i][j] = 0ull;

    for (int k0 = 0; k0 < K; k0 += BK) {
#pragma unroll
        for (int i = 0; i < 2; i++) {
            int f = tid + i * 256;
            int r = f >> 2;
            int c = (f & 3) << 2;
            float4 va = *reinterpret_cast<const float4*>(A + (size_t)r * K + k0 + c);
            As[c + 0][r] = va.x; As[c + 1][r] = va.y;
            As[c + 2][r] = va.z; As[c + 3][r] = va.w;
            float4 vb = *reinterpret_cast<const float4*>(B + (size_t)r * K + k0 + c);
            Bs[c + 0][r] = vb.x; Bs[c + 1][r] = vb.y;
            Bs[c + 2][r] = vb.z; Bs[c + 3][r] = vb.w;
        }
        __syncthreads();
#pragma unroll
        for (int kk = 0; kk < BK; kk++) {
            float4 a0 = *reinterpret_cast<const float4*>(&As[kk][tr * 8]);
            float4 a1 = *reinterpret_cast<const float4*>(&As[kk][tr * 8 + 4]);
            float4 b0 = *reinterpret_cast<const float4*>(&Bs[kk][tc * 8]);
            float4 b1 = *reinterpret_cast<const float4*>(&Bs[kk][tc * 8 + 4]);
            unsigned long long bb[4] = {pk2(b0.x, b0.y), pk2(b0.z, b0.w),
                                        pk2(b1.x, b1.y), pk2(b1.z, b1.w)};
            float af[8] = {a0.x, a0.y, a0.z, a0.w, a1.x, a1.y, a1.z, a1.w};
#pragma unroll
            for (int i = 0; i < 8; i++) {
                unsigned long long aa = pk2(af[i], af[i]);
#pragma unroll
                for (int j = 0; j < 4; j++) acc[i][j] = ffma2(aa, bb[j], acc[i][j]);
            }
        }
        __syncthreads();
    }

#pragma unroll
    for (int i = 0; i < 8; i++) {
        size_t row = (size_t)blockIdx.y * BM + tr * 8 + i;
#pragma unroll
        for (int j = 0; j < 4; j++) {
            int col = blockIdx.x * BN + tc * 8 + 2 * j;
            float lo, hi;
            upk2(acc[i][j], lo, hi);
            lo *= alpha; hi *= alpha;
            if (bias) { lo += bias[col]; hi += bias[col + 1]; }
            size_t idx = row * N + col;
            if (res) { lo += res[idx]; hi += res[idx + 1]; }
            float2 o; o.x = lo; o.y = hi;
            *reinterpret_cast<float2*>(C + idx) = o;
        }
    }
}

// ---------------------------------------------------------------------------
// NN GEMM: C[m,n] = sum_k A[m,k]*B[k,n]   (A lda=K, B ldb=N)
// ---------------------------------------------------------------------------
__global__ void __launch_bounds__(256, 2) gemm_nn(
    const float* __restrict__ A, const float* __restrict__ B,
    float* __restrict__ C,
    int N, int K,
    size_t sA, size_t sB, size_t sC)
{
    __shared__ float As[BK][BM + 4];
    __shared__ float Bs[BK][BN + 4];
    const int tid = threadIdx.x;
    A += blockIdx.z * sA + (size_t)blockIdx.y * BM * K;
    B += blockIdx.z * sB;
    C += blockIdx.z * sC;

    const int tr = tid >> 4, tc = tid & 15;
    unsigned long long acc[8][4];
#pragma unroll
    for (int i = 0; i < 8; i++)
#pragma unroll
        for (int j = 0; j < 4; j++) acc[i][j] = 0ull;

    for (int k0 = 0; k0 < K; k0 += BK) {
#pragma unroll
        for (int i = 0; i < 2; i++) {
            int f = tid + i * 256;
            {   // A tile 128x16, transpose into As
                int r = f >> 2;
                int c = (f & 3) << 2;
                float4 va = *reinterpret_cast<const float4*>(A + (size_t)r * K + k0 + c);
                As[c + 0][r] = va.x; As[c + 1][r] = va.y;
                As[c + 2][r] = va.z; As[c + 3][r] = va.w;
            }
            {   // B tile 16x128, direct
                int r = f >> 5;
                int c = (f & 31) << 2;
                float4 vb = *reinterpret_cast<const float4*>(
                    B + (size_t)(k0 + r) * N + blockIdx.x * BN + c);
                *reinterpret_cast<float4*>(&Bs[r][c]) = vb;
            }
        }
        __syncthreads();
#pragma unroll
        for (int kk = 0; kk < BK; kk++) {
            float4 a0 = *reinterpret_cast<const float4*>(&As[kk][tr * 8]);
            float4 a1 = *reinterpret_cast<const float4*>(&As[kk][tr * 8 + 4]);
            float4 b0 = *reinterpret_cast<const float4*>(&Bs[kk][tc * 8]);
            float4 b1 = *reinterpret_cast<const float4*>(&Bs[kk][tc * 8 + 4]);
            unsigned long long bb[4] = {pk2(b0.x, b0.y), pk2(b0.z, b0.w),
                                        pk2(b1.x, b1.y), pk2(b1.z, b1.w)};
            float af[8] = {a0.x, a0.y, a0.z, a0.w, a1.x, a1.y, a1.z, a1.w};
#pragma unroll
            for (int i = 0; i < 8; i++) {
                unsigned long long aa = pk2(af[i], af[i]);
#pragma unroll
                for (int j = 0; j < 4; j++) acc[i][j] = ffma2(aa, bb[j], acc[i][j]);
            }
        }
        __syncthreads();
    }

#pragma unroll
    for (int i = 0; i < 8; i++) {
        size_t row = (size_t)blockIdx.y * BM + tr * 8 + i;
#pragma unroll
        for (int j = 0; j < 4; j++) {
            int col = blockIdx.x * BN + tc * 8 + 2 * j;
            float lo, hi;
            upk2(acc[i][j], lo, hi);
            size_t idx = row * N + col;
            float2 o; o.x = lo; o.y = hi;
            *reinterpret_cast<float2*>(C + idx) = o;
        }
    }
}

// ---------------------------------------------------------------------------
// Row softmax over S=2048, one block (256 thr) per row
// ---------------------------------------------------------------------------
__global__ void __launch_bounds__(256) softmax_k(float* __restrict__ logits) {
    float* p = logits + (size_t)blockIdx.x * Ss;
    const int tid = threadIdx.x;
    float v[8];
#pragma unroll
    for (int i = 0; i < 8; i++) v[i] = p[tid + 256 * i];

    float m = v[0];
#pragma unroll
    for (int i = 1; i < 8; i++) m = fmaxf(m, v[i]);
#pragma unroll
    for (int o = 16; o; o >>= 1) m = fmaxf(m, __shfl_xor_sync(0xffffffffu, m, o));
    __shared__ float rmax[8], rsum[8];
    if ((tid & 31) == 0) rmax[tid >> 5] = m;
    __syncthreads();
#pragma unroll
    for (int i = 0; i < 8; i++) m = fmaxf(m, rmax[i]);

    float s = 0.f;
#pragma unroll
    for (int i = 0; i < 8; i++) { v[i] = expf(v[i] - m); s += v[i]; }
#pragma unroll
    for (int o = 16; o; o >>= 1) s += __shfl_xor_sync(0xffffffffu, s, o);
    if ((tid & 31) == 0) rsum[tid >> 5] = s;
    __syncthreads();
    s = 0.f;
#pragma unroll
    for (int i = 0; i < 8; i++) s += rsum[i];
    float inv = 1.f / s;
#pragma unroll
    for (int i = 0; i < 8; i++) p[tid + 256 * i] = v[i] * inv;
}

// ---------------------------------------------------------------------------
// LayerNorm(+relu) in-place over C=1024, one block (256 thr) per row
// ---------------------------------------------------------------------------
__global__ void __launch_bounds__(256) ln_relu_k(
    float* __restrict__ h, const float* __restrict__ g, const float* __restrict__ b)
{
    float* p = h + (size_t)blockIdx.x * Cc;
    const int tid = threadIdx.x;
    float v[4];
    float s = 0.f, ss = 0.f;
#pragma unroll
    for (int i = 0; i < 4; i++) {
        v[i] = p[tid + 256 * i];
        s += v[i];
        ss += v[i] * v[i];
    }
#pragma unroll
    for (int o = 16; o; o >>= 1) {
        s  += __shfl_xor_sync(0xffffffffu, s, o);
        ss += __shfl_xor_sync(0xffffffffu, ss, o);
    }
    __shared__ float r1[8], r2[8];
    if ((tid & 31) == 0) { r1[tid >> 5] = s; r2[tid >> 5] = ss; }
    __syncthreads();
    s = 0.f; ss = 0.f;
#pragma unroll
    for (int i = 0; i < 8; i++) { s += r1[i]; ss += r2[i]; }
    float mean = s * (1.f / Cc);
    float var  = ss * (1.f / Cc) - mean * mean;
    float inv  = rsqrtf(var + 1e-5f);
#pragma unroll
    for (int i = 0; i < 4; i++) {
        int c = tid + 256 * i;
        float y = (v[i] - mean) * inv * g[c] + b[c];
        p[c] = fmaxf(y, 0.f);
    }
}

// ---------------------------------------------------------------------------
extern "C" void kernel_launch(void* const* d_in, const int* in_sizes, int n_in,
                              void* d_out, int out_size)
{
    (void)in_sizes; (void)n_in; (void)out_size;
    const float* x       = (const float*)d_in[0];
    const float* lfb     = (const float*)d_in[1];
    const float* theta_w = (const float*)d_in[2];
    const float* theta_b = (const float*)d_in[3];
    const float* phi_w   = (const float*)d_in[4];
    const float* phi_b   = (const float*)d_in[5];
    const float* gi_w    = (const float*)d_in[6];
    const float* gi_b    = (const float*)d_in[7];
    const float* ln_g    = (const float*)d_in[8];
    const float* ln_b    = (const float*)d_in[9];
    const float* fc_w    = (const float*)d_in[10];
    const float* fc_b    = (const float*)d_in[11];
    float* out = (float*)d_out;

    float *theta, *phi, *gi, *logits, *att;
    cudaGetSymbolAddress((void**)&theta,  g_theta);
    cudaGetSymbolAddress((void**)&phi,    g_phi);
    cudaGetSymbolAddress((void**)&gi,     g_gi);
    cudaGetSymbolAddress((void**)&logits, g_logits);
    cudaGetSymbolAddress((void**)&att,    g_att);

    dim3 blk(256);
    const float scale = 32.0f; // sqrt(C)

    // theta = x @ theta_w^T + theta_b          [8192,1024]
    gemm_nt<<<dim3(Cc / BN, (Bv * Tt) / BM, 1), blk>>>(
        x, theta_w, theta_b, nullptr, theta, Cc, Cc, 1.f, 0, 0, 0);
    // phi / gi from lfb                        [16384,1024]
    gemm_nt<<<dim3(Cc / BN, (Bv * Ss) / BM, 1), blk>>>(
        lfb, phi_w, phi_b, nullptr, phi, Cc, Cc, 1.f, 0, 0, 0);
    gemm_nt<<<dim3(Cc / BN, (Bv * Ss) / BM, 1), blk>>>(
        lfb, gi_w, gi_b, nullptr, gi, Cc, Cc, 1.f, 0, 0, 0);
    // logits[b] = scale * theta[b] @ phi[b]^T  [1024,2048] x8
    gemm_nt<<<dim3(Ss / BN, Tt / BM, Bv), blk>>>(
        theta, phi, nullptr, nullptr, logits, Ss, Cc, scale,
        (size_t)Tt * Cc, (size_t)Ss * Cc, (size_t)Tt * Ss);
    // softmax rows
    softmax_k<<<Bv * Tt, blk>>>(logits);
    // att[b] = attn[b] @ gi[b]                 [1024,1024] x8
    gemm_nn<<<dim3(Cc / BN, Tt / BM, Bv), blk>>>(
        logits, gi, att, Cc, Ss,
        (size_t)Tt * Ss, (size_t)Ss * Cc, (size_t)Tt * Cc);
    // LN + relu in place
    ln_relu_k<<<Bv * Tt, blk>>>(att, ln_g, ln_b);
    // out = att @ fc_w^T + fc_b + x
    gemm_nt<<<dim3(Cc / BN, (Bv * Tt) / BM, 1), blk>>>(
        att, fc_w, fc_b, x, out, Cc, Cc, 1.f, 0, 0, 0);
}

// round 5
// speedup vs baseline: 1.5364x; 1.5364x over previous
#include <cuda_runtime.h>
#include <math.h>
#include <stdint.h>

// ---------------------------------------------------------------------------
// _NLBlock on GB300 via LEGACY tensor path (mma.sync tf32, baseline PTX —
// harness compiles for compute_103 so tcgen05/sm_103a features are
// unavailable).  High-precision GEMMs use 3xTF32 hi/lo operand splitting.
// ---------------------------------------------------------------------------

#define Bv 8
#define Tt 1024
#define Ss 2048
#define Cc 1024

__device__ float g_theta [Bv * Tt * Cc];
__device__ float g_phi   [Bv * Ss * Cc];
__device__ float g_gi    [Bv * Ss * Cc];
__device__ float g_logits[Bv * Tt * Ss];
__device__ float g_att   [Bv * Tt * Cc];

__device__ __forceinline__ uint32_t fu(float f) { return __float_as_uint(f); }

__device__ __forceinline__ float rtf32(float x) {   // round-to-nearest tf32
    uint32_t u;
    asm("cvt.rna.tf32.f32 %0, %1;" : "=r"(u) : "f"(x));
    return __uint_as_float(u);
}

__device__ __forceinline__ void mma8(float* d, uint32_t a0, uint32_t a1,
                                     uint32_t a2, uint32_t a3,
                                     uint32_t b0, uint32_t b1) {
    asm("mma.sync.aligned.m16n8k8.row.col.f32.tf32.tf32.f32 "
        "{%0,%1,%2,%3}, {%4,%5,%6,%7}, {%8,%9}, {%0,%1,%2,%3};"
        : "+f"(d[0]), "+f"(d[1]), "+f"(d[2]), "+f"(d[3])
        : "r"(a0), "r"(a1), "r"(a2), "r"(a3), "r"(b0), "r"(b1));
}

// smem tile format: 128 rows x 128B. Element (row,k) [k in 0..31] stored at
// byte ( 4*((k&3)*8 + (k>>2)) ) ^ ((row&7)<<4)  within the row.
// => a fragment gather for all 4 k-steps of a row is two LDS.128.
#define ROWB 128

// ---------------------------------------------------------------------------
// Tensor-core GEMM, CTA tile 128x128x32, 256 thr (8 warps, 2Mx4N, 64x32 warp)
//   SPLIT: hi/lo 3xTF32 (fp32-grade)   TB: B source is [K, ldb] row-major
//   C = alpha * A@B^T (+bias[n]) (+res)
// ---------------------------------------------------------------------------
template <bool SPLIT, bool TB>
__global__ void __launch_bounds__(256, 1) gemm_mma(
    const float* __restrict__ A, const float* __restrict__ B,
    const float* __restrict__ bias, const float* __restrict__ res,
    float* __restrict__ C,
    int N, int K, int ldb, float alpha,
    size_t sA, size_t sB, size_t sC)
{
    extern __shared__ char sm[];
    const int tid  = threadIdx.x;
    const int lane = tid & 31;
    const int wid  = tid >> 5;
    const int wm   = wid >> 2;      // 0..1
    const int wn   = wid & 3;       // 0..3
    const int n0   = blockIdx.x * 128;

    const float* Ag = A + blockIdx.z * sA + (size_t)blockIdx.y * 128 * K;
    const float* Bg = TB ? (B + blockIdx.z * sB)
                         : (B + blockIdx.z * sB + (size_t)n0 * K);
    float* Cg = C + blockIdx.z * sC;
    const float* Rg = res ? res + blockIdx.z * sC : nullptr;

    float* sbias = (float*)sm;                       // 512 B
    char* AH = sm + 1024;
    char* AL = AH + 16384;
    char* BH = SPLIT ? (AL + 16384) : (AH + 16384);
    char* BL = BH + 16384;

    if (bias && tid < 128) sbias[tid] = bias[n0 + tid];

    float acc[4][4][4];
#pragma unroll
    for (int mt = 0; mt < 4; mt++)
#pragma unroll
        for (int nt = 0; nt < 4; nt++)
#pragma unroll
            for (int e = 0; e < 4; e++) acc[mt][nt][e] = 0.f;

    float4 av[4], bv[4];
    const int kq = tid & 7, nq = tid >> 3;   // TB loader mapping

#define LOAD_STAGE(K0)                                                        \
    {                                                                         \
        _Pragma("unroll")                                                     \
        for (int i = 0; i < 4; i++) {                                         \
            int v = i * 256 + tid;                                            \
            int r = v >> 3, c4 = v & 7;                                       \
            av[i] = *(const float4*)(Ag + (size_t)r * K + (K0) + c4 * 4);     \
        }                                                                     \
        if (!TB) {                                                            \
            _Pragma("unroll")                                                 \
            for (int i = 0; i < 4; i++) {                                     \
                int v = i * 256 + tid;                                        \
                int r = v >> 3, c4 = v & 7;                                   \
                bv[i] = *(const float4*)(Bg + (size_t)r * K + (K0) + c4 * 4); \
            }                                                                 \
        } else {                                                              \
            _Pragma("unroll")                                                 \
            for (int i = 0; i < 4; i++)                                       \
                bv[i] = *(const float4*)(                                     \
                    Bg + (size_t)((K0) + kq * 4 + i) * ldb + n0 + nq * 4);    \
        }                                                                     \
    }

    const int NC = K / 32;
    LOAD_STAGE(0);

    for (int ck = 0; ck < NC; ck++) {
        __syncthreads();   // previous compute done; stage free

        // ---- STS (with split / tf32 rounding) ----
#pragma unroll
        for (int i = 0; i < 4; i++) {
            int v = i * 256 + tid;
            int r = v >> 3, c4 = v & 7;
            const float* e = (const float*)&av[i];
            uint32_t sw = (uint32_t)((r & 7) << 4);
#pragma unroll
            for (int q = 0; q < 4; q++) {
                uint32_t o = (uint32_t)(32 * q + 4 * c4) ^ sw;
                float x = e[q];
                if (SPLIT) {
                    float h = __uint_as_float(fu(x) & 0xFFFFE000u);
                    *(float*)(AH + r * ROWB + o) = h;
                    *(float*)(AL + r * ROWB + o) = x - h;
                } else {
                    *(float*)(AH + r * ROWB + o) = rtf32(x);
                }
            }
        }
        if (!TB) {
#pragma unroll
            for (int i = 0; i < 4; i++) {
                int v = i * 256 + tid;
                int r = v >> 3, c4 = v & 7;
                const float* e = (const float*)&bv[i];
                uint32_t sw = (uint32_t)((r & 7) << 4);
#pragma unroll
                for (int q = 0; q < 4; q++) {
                    uint32_t o = (uint32_t)(32 * q + 4 * c4) ^ sw;
                    float x = e[q];
                    if (SPLIT) {
                        float h = __uint_as_float(fu(x) & 0xFFFFE000u);
                        *(float*)(BH + r * ROWB + o) = h;
                        *(float*)(BL + r * ROWB + o) = x - h;
                    } else {
                        *(float*)(BH + r * ROWB + o) = rtf32(x);
                    }
                }
            }
        } else {
#pragma unroll
            for (int i = 0; i < 4; i++) {        // k index = ck*32 + kq*4 + i
                const float* e = (const float*)&bv[i];
#pragma unroll
                for (int j = 0; j < 4; j++) {    // n row = nq*4 + j
                    int row = nq * 4 + j;
                    uint32_t o = (uint32_t)(32 * i + 4 * kq)
                               ^ (uint32_t)((row & 7) << 4);
                    *(float*)(BH + row * ROWB + o) = rtf32(e[j]);
                }
            }
        }
        __syncthreads();

        if (ck + 1 < NC) LOAD_STAGE((ck + 1) * 32);

        // ---- compute: gather fragments, issue MMAs ----
        float4 bhq[4][2], blq[4][2];
#pragma unroll
        for (int nt = 0; nt < 4; nt++) {
            int row = wn * 32 + nt * 8 + (lane >> 2);
            uint32_t sw = (uint32_t)((row & 7) << 4);
            uint32_t o0 = (uint32_t)((lane & 3) * 32) ^ sw;
            uint32_t o1 = (uint32_t)((lane & 3) * 32 + 16) ^ sw;
            bhq[nt][0] = *(const float4*)(BH + row * ROWB + o0);
            bhq[nt][1] = *(const float4*)(BH + row * ROWB + o1);
            if (SPLIT) {
                blq[nt][0] = *(const float4*)(BL + row * ROWB + o0);
                blq[nt][1] = *(const float4*)(BL + row * ROWB + o1);
            }
        }
#pragma unroll
        for (int mt = 0; mt < 4; mt++) {
            float4 ahq[2][2], alq[2][2];
#pragma unroll
            for (int rr = 0; rr < 2; rr++) {
                int row = wm * 64 + mt * 16 + (lane >> 2) + rr * 8;
                uint32_t sw = (uint32_t)((row & 7) << 4);
                uint32_t o0 = (uint32_t)((lane & 3) * 32) ^ sw;
                uint32_t o1 = (uint32_t)((lane & 3) * 32 + 16) ^ sw;
                ahq[rr][0] = *(const float4*)(AH + row * ROWB + o0);
                ahq[rr][1] = *(const float4*)(AH + row * ROWB + o1);
                if (SPLIT) {
                    alq[rr][0] = *(const float4*)(AL + row * ROWB + o0);
                    alq[rr][1] = *(const float4*)(AL + row * ROWB + o1);
                }
            }
            const float* ah = (const float*)ahq;   // [rr][q][4]
            const float* al = (const float*)alq;
#pragma unroll
            for (int j = 0; j < 4; j++) {
                const int q = j >> 1, e = (j & 1) * 2;
                uint32_t aH0 = fu(ah[q * 4 + e]),     aH1 = fu(ah[8 + q * 4 + e]);
                uint32_t aH2 = fu(ah[q * 4 + e + 1]), aH3 = fu(ah[8 + q * 4 + e + 1]);
                uint32_t aL0 = 0, aL1 = 0, aL2 = 0, aL3 = 0;
                if (SPLIT) {
                    aL0 = fu(al[q * 4 + e]);     aL1 = fu(al[8 + q * 4 + e]);
                    aL2 = fu(al[q * 4 + e + 1]); aL3 = fu(al[8 + q * 4 + e + 1]);
                }
#pragma unroll
                for (int nt = 0; nt < 4; nt++) {
                    const float* bh = (const float*)&bhq[nt][0];
                    uint32_t bH0 = fu(bh[q * 4 + e]), bH1 = fu(bh[q * 4 + e + 1]);
                    mma8(acc[mt][nt], aH0, aH1, aH2, aH3, bH0, bH1);
                    if (SPLIT) {
                        const float* bl = (const float*)&blq[nt][0];
                        uint32_t bL0 = fu(bl[q * 4 + e]);
                        uint32_t bL1 = fu(bl[q * 4 + e + 1]);
                        mma8(acc[mt][nt], aL0, aL1, aL2, aL3, bH0, bH1);
                        mma8(acc[mt][nt], aH0, aH1, aH2, aH3, bL0, bL1);
                    }
                }
            }
        }
    }

    // ---- epilogue ----
#pragma unroll
    for (int mt = 0; mt < 4; mt++) {
        size_t m0 = (size_t)blockIdx.y * 128 + wm * 64 + mt * 16 + (lane >> 2);
#pragma unroll
        for (int nt = 0; nt < 4; nt++) {
            int cl = wn * 32 + nt * 8 + (lane & 3) * 2;   // col within tile
            int col = n0 + cl;
            float v0 = acc[mt][nt][0] * alpha, v1 = acc[mt][nt][1] * alpha;
            float v2 = acc[mt][nt][2] * alpha, v3 = acc[mt][nt][3] * alpha;
            if (bias) {
                float b0 = sbias[cl], b1 = sbias[cl + 1];
                v0 += b0; v1 += b1; v2 += b0; v3 += b1;
            }
            size_t i0 = m0 * N + col, i1 = (m0 + 8) * N + col;
            if (Rg) {
                v0 += Rg[i0]; v1 += Rg[i0 + 1];
                v2 += Rg[i1]; v3 += Rg[i1 + 1];
            }
            float2 w0; w0.x = v0; w0.y = v1;
            float2 w1; w1.x = v2; w1.y = v3;
            *(float2*)(Cg + i0) = w0;
            *(float2*)(Cg + i1) = w1;
        }
    }
#undef LOAD_STAGE
}

// ---------------------------------------------------------------------------
// fast exp via FMA-pipe polynomial (avoids MUFU bottleneck); x <= 0
// ---------------------------------------------------------------------------
__device__ __forceinline__ float fexp(float x) {
    float t = fmaxf(x * 1.4426950408889634f, -126.f);
    float n = rintf(t);
    float f = t - n;
    float p = 0.0013333558f;
    p = fmaf(p, f, 0.0096181291f);
    p = fmaf(p, f, 0.0555041087f);
    p = fmaf(p, f, 0.2402265069f);
    p = fmaf(p, f, 0.6931471806f);
    p = fmaf(p, f, 1.0f);
    return p * __int_as_float(((int)n + 127) << 23);
}

__global__ void __launch_bounds__(256) softmax_k(float* __restrict__ logits) {
    float* p = logits + (size_t)blockIdx.x * Ss;
    const int tid = threadIdx.x;
    float v[8];
#pragma unroll
    for (int i = 0; i < 8; i++) v[i] = p[tid + 256 * i];
    float m = v[0];
#pragma unroll
    for (int i = 1; i < 8; i++) m = fmaxf(m, v[i]);
#pragma unroll
    for (int o = 16; o; o >>= 1) m = fmaxf(m, __shfl_xor_sync(0xffffffffu, m, o));
    __shared__ float rmax[8], rsum[8];
    if ((tid & 31) == 0) rmax[tid >> 5] = m;
    __syncthreads();
#pragma unroll
    for (int i = 0; i < 8; i++) m = fmaxf(m, rmax[i]);
    float s = 0.f;
#pragma unroll
    for (int i = 0; i < 8; i++) { v[i] = fexp(v[i] - m); s += v[i]; }
#pragma unroll
    for (int o = 16; o; o >>= 1) s += __shfl_xor_sync(0xffffffffu, s, o);
    if ((tid & 31) == 0) rsum[tid >> 5] = s;
    __syncthreads();
    s = 0.f;
#pragma unroll
    for (int i = 0; i < 8; i++) s += rsum[i];
    float inv = 1.f / s;
#pragma unroll
    for (int i = 0; i < 8; i++) p[tid + 256 * i] = v[i] * inv;
}

__global__ void __launch_bounds__(256) ln_relu_k(
    float* __restrict__ h, const float* __restrict__ g, const float* __restrict__ b)
{
    float* p = h + (size_t)blockIdx.x * Cc;
    const int tid = threadIdx.x;
    float v[4];
    float s = 0.f, ss = 0.f;
#pragma unroll
    for (int i = 0; i < 4; i++) {
        v[i] = p[tid + 256 * i];
        s += v[i];
        ss += v[i] * v[i];
    }
#pragma unroll
    for (int o = 16; o; o >>= 1) {
        s  += __shfl_xor_sync(0xffffffffu, s, o);
        ss += __shfl_xor_sync(0xffffffffu, ss, o);
    }
    __shared__ float r1[8], r2[8];
    if ((tid & 31) == 0) { r1[tid >> 5] = s; r2[tid >> 5] = ss; }
    __syncthreads();
    s = 0.f; ss = 0.f;
#pragma unroll
    for (int i = 0; i < 8; i++) { s += r1[i]; ss += r2[i]; }
    float mean = s * (1.f / Cc);
    float var  = ss * (1.f / Cc) - mean * mean;
    float inv  = rsqrtf(var + 1e-5f);
#pragma unroll
    for (int i = 0; i < 4; i++) {
        int c = tid + 256 * i;
        float y = (v[i] - mean) * inv * g[c] + b[c];
        p[c] = fmaxf(y, 0.f);
    }
}

// ---------------------------------------------------------------------------
extern "C" void kernel_launch(void* const* d_in, const int* in_sizes, int n_in,
                              void* d_out, int out_size)
{
    (void)in_sizes; (void)n_in; (void)out_size;
    const float* x       = (const float*)d_in[0];
    const float* lfb     = (const float*)d_in[1];
    const float* theta_w = (const float*)d_in[2];
    const float* theta_b = (const float*)d_in[3];
    const float* phi_w   = (const float*)d_in[4];
    const float* phi_b   = (const float*)d_in[5];
    const float* gi_w    = (const float*)d_in[6];
    const float* gi_b    = (const float*)d_in[7];
    const float* ln_g    = (const float*)d_in[8];
    const float* ln_b    = (const float*)d_in[9];
    const float* fc_w    = (const float*)d_in[10];
    const float* fc_b    = (const float*)d_in[11];
    float* out = (float*)d_out;

    float *theta, *phi, *gi, *logits, *att;
    cudaGetSymbolAddress((void**)&theta,  g_theta);
    cudaGetSymbolAddress((void**)&phi,    g_phi);
    cudaGetSymbolAddress((void**)&gi,     g_gi);
    cudaGetSymbolAddress((void**)&logits, g_logits);
    cudaGetSymbolAddress((void**)&att,    g_att);

    const int SMEM_SPLIT  = 1024 + 4 * 16384;   // 66560
    const int SMEM_SINGLE = 1024 + 2 * 16384;   // 33792
    cudaFuncSetAttribute(gemm_mma<true,  false>,
        cudaFuncAttributeMaxDynamicSharedMemorySize, SMEM_SPLIT);
    cudaFuncSetAttribute(gemm_mma<false, false>,
        cudaFuncAttributeMaxDynamicSharedMemorySize, SMEM_SINGLE);
    cudaFuncSetAttribute(gemm_mma<false, true>,
        cudaFuncAttributeMaxDynamicSharedMemorySize, SMEM_SINGLE);

    dim3 blk(256);
    const float scale = 32.0f;   // sqrt(C)

    // theta = x @ theta_w^T + theta_b               [8192,1024]  (split)
    gemm_mma<true, false><<<dim3(8, 64, 1), blk, SMEM_SPLIT>>>(
        x, theta_w, theta_b, nullptr, theta, Cc, Cc, 0, 1.f, 0, 0, 0);
    // phi = lfb @ phi_w^T + phi_b                   [16384,1024] (split)
    gemm_mma<true, false><<<dim3(8, 128, 1), blk, SMEM_SPLIT>>>(
        lfb, phi_w, phi_b, nullptr, phi, Cc, Cc, 0, 1.f, 0, 0, 0);
    // gi = lfb @ gi_w^T + gi_b                      [16384,1024] (single)
    gemm_mma<false, false><<<dim3(8, 128, 1), blk, SMEM_SINGLE>>>(
        lfb, gi_w, gi_b, nullptr, gi, Cc, Cc, 0, 1.f, 0, 0, 0);
    // logits[b] = 32 * theta[b] @ phi[b]^T          [1024,2048]x8 (split)
    gemm_mma<true, false><<<dim3(16, 8, Bv), blk, SMEM_SPLIT>>>(
        theta, phi, nullptr, nullptr, logits, Ss, Cc, 0, scale,
        (size_t)Tt * Cc, (size_t)Ss * Cc, (size_t)Tt * Ss);
    softmax_k<<<Bv * Tt, blk>>>(logits);
    // att[b] = attn[b] @ gi[b]   (B = gi is [K=2048, N=1024] -> TB, single)
    gemm_mma<false, true><<<dim3(8, 8, Bv), blk, SMEM_SINGLE>>>(
        logits, gi, nullptr, nullptr, att, Cc, Ss, Cc, 1.f,
        (size_t)Tt * Ss, (size_t)Ss * Cc, (size_t)Tt * Cc);
    ln_relu_k<<<Bv * Tt, blk>>>(att, ln_g, ln_b);
    // out = relu(LN(att)) @ fc_w^T + fc_b + x       [8192,1024]  (single)
    gemm_mma<false, false><<<dim3(8, 64, 1), blk, SMEM_SINGLE>>>(
        att, fc_w, fc_b, x, out, Cc, Cc, 0, 1.f, 0, 0, 0);
}

// round 7
// speedup vs baseline: 1.7570x; 1.1436x over previous
#include <cuda_runtime.h>
#include <math.h>
#include <stdint.h>

// ---------------------------------------------------------------------------
// _NLBlock on GB300 via legacy mma.sync tf32 (compute_103-safe).
// R5: raw-fp32 smem stages, split/round at fragment load, 3-stage pipeline
// with a single __syncthreads per K-chunk.
// ---------------------------------------------------------------------------

#define Bv 8
#define Tt 1024
#define Ss 2048
#define Cc 1024

__device__ float g_theta [Bv * Tt * Cc];
__device__ float g_phi   [Bv * Ss * Cc];
__device__ float g_gi    [Bv * Ss * Cc];
__device__ float g_logits[Bv * Tt * Ss];
__device__ float g_att   [Bv * Tt * Cc];

__device__ __forceinline__ uint32_t fu(float f) { return __float_as_uint(f); }

__device__ __forceinline__ float rtf32(float x) {
    uint32_t u;
    asm("cvt.rna.tf32.f32 %0, %1;" : "=r"(u) : "f"(x));
    return __uint_as_float(u);
}

__device__ __forceinline__ void mma8(float* d, uint32_t a0, uint32_t a1,
                                     uint32_t a2, uint32_t a3,
                                     uint32_t b0, uint32_t b1) {
    asm("mma.sync.aligned.m16n8k8.row.col.f32.tf32.tf32.f32 "
        "{%0,%1,%2,%3}, {%4,%5,%6,%7}, {%8,%9}, {%0,%1,%2,%3};"
        : "+f"(d[0]), "+f"(d[1]), "+f"(d[2]), "+f"(d[3])
        : "r"(a0), "r"(a1), "r"(a2), "r"(a3), "r"(b0), "r"(b1));
}

// smem tile: 128 rows x 128B. Element (row,k), k in [0,32):
//   byte offset = (4*((k&3)*8 + (k>>2))) ^ ((row&7)<<4)
// -> all 4 k-steps of a row gather as two LDS.128.
#define ROWB 128
constexpr int STAGE  = 32768;        // A 16KB + B 16KB, raw fp32
constexpr int NSTG   = 3;
constexpr int SMEM_ALL = 1024 + NSTG * STAGE;   // 99328

// ---------------------------------------------------------------------------
// CTA tile 128x128x32, 256 thr (8 warps: 2M x 4N, 64x32 per warp)
//   SPLIT: hi/lo 3xTF32 at fragment-load   TB: B source [K, ldb] row-major
//   C = alpha * A@B^T (+bias[n]) (+res)
// ---------------------------------------------------------------------------
template <bool SPLIT, bool TB>
__global__ void __launch_bounds__(256, 1) gemm_mma(
    const float* __restrict__ A, const float* __restrict__ B,
    const float* __restrict__ bias, const float* __restrict__ res,
    float* __restrict__ C,
    int N, int K, int ldb, float alpha,
    size_t sA, size_t sB, size_t sC)
{
    extern __shared__ char sm[];
    const int tid  = threadIdx.x;
    const int lane = tid & 31;
    const int wid  = tid >> 5;
    const int wm   = wid >> 2;
    const int wn   = wid & 3;
    const int n0   = blockIdx.x * 128;

    const float* Ag = A + blockIdx.z * sA + (size_t)blockIdx.y * 128 * K;
    const float* Bg = TB ? (B + blockIdx.z * sB)
                         : (B + blockIdx.z * sB + (size_t)n0 * K);
    float* Cg = C + blockIdx.z * sC;
    const float* Rg = res ? res + blockIdx.z * sC : nullptr;

    float* sbias = (float*)sm;
    char* SBUF = sm + 1024;

    if (bias && tid < 128) sbias[tid] = bias[n0 + tid];

    float acc[4][4][4];
#pragma unroll
    for (int mt = 0; mt < 4; mt++)
#pragma unroll
        for (int nt = 0; nt < 4; nt++)
#pragma unroll
            for (int e = 0; e < 4; e++) acc[mt][nt][e] = 0.f;

    float4 av[4], bv[4];
    const int kq = tid & 7, nq = tid >> 3;

#define LDG_STAGE(K0)                                                         \
    {                                                                         \
        _Pragma("unroll")                                                     \
        for (int i = 0; i < 4; i++) {                                         \
            int v = i * 256 + tid;                                            \
            int r = v >> 3, c4 = v & 7;                                       \
            av[i] = *(const float4*)(Ag + (size_t)r * K + (K0) + c4 * 4);     \
        }                                                                     \
        if (!TB) {                                                            \
            _Pragma("unroll")                                                 \
            for (int i = 0; i < 4; i++) {                                     \
                int v = i * 256 + tid;                                        \
                int r = v >> 3, c4 = v & 7;                                   \
                bv[i] = *(const float4*)(Bg + (size_t)r * K + (K0) + c4 * 4); \
            }                                                                 \
        } else {                                                              \
            _Pragma("unroll")                                                 \
            for (int i = 0; i < 4; i++)                                       \
                bv[i] = *(const float4*)(                                     \
                    Bg + (size_t)((K0) + kq * 4 + i) * ldb + n0 + nq * 4);    \
        }                                                                     \
    }

    // raw fp32 store (split kernels defer split to load; single rounds here)
#define STS_STAGE(S)                                                          \
    {                                                                         \
        char* AS = SBUF + (S) * STAGE;                                        \
        char* BS = AS + 16384;                                                \
        _Pragma("unroll")                                                     \
        for (int i = 0; i < 4; i++) {                                         \
            int v = i * 256 + tid;                                            \
            int r = v >> 3, c4 = v & 7;                                       \
            const float* e = (const float*)&av[i];                            \
            uint32_t sw = (uint32_t)((r & 7) << 4);                           \
            _Pragma("unroll")                                                 \
            for (int q = 0; q < 4; q++) {                                     \
                uint32_t o = (uint32_t)(32 * q + 4 * c4) ^ sw;                \
                *(float*)(AS + r * ROWB + o) = SPLIT ? e[q] : rtf32(e[q]);    \
            }                                                                 \
        }                                                                     \
        if (!TB) {                                                            \
            _Pragma("unroll")                                                 \
            for (int i = 0; i < 4; i++) {                                     \
                int v = i * 256 + tid;                                        \
                int r = v >> 3, c4 = v & 7;                                   \
                const float* e = (const float*)&bv[i];                        \
                uint32_t sw = (uint32_t)((r & 7) << 4);                       \
                _Pragma("unroll")                                             \
                for (int q = 0; q < 4; q++) {                                 \
                    uint32_t o = (uint32_t)(32 * q + 4 * c4) ^ sw;            \
                    *(float*)(BS + r * ROWB + o) =                            \
                        SPLIT ? e[q] : rtf32(e[q]);                           \
                }                                                             \
            }                                                                 \
        } else {                                                              \
            _Pragma("unroll")                                                 \
            for (int i = 0; i < 4; i++) {                                     \
                const float* e = (const float*)&bv[i];                        \
                _Pragma("unroll")                                             \
                for (int j = 0; j < 4; j++) {                                 \
                    int row = nq * 4 + j;                                     \
                    uint32_t o = (uint32_t)(32 * i + 4 * kq)                  \
                               ^ (uint32_t)((row & 7) << 4);                  \
                    *(float*)(BS + row * ROWB + o) =                          \
                        SPLIT ? e[j] : rtf32(e[j]);                           \
                }                                                             \
            }                                                                 \
        }                                                                     \
    }

    const int NC = K / 32;

    // prologue: stage0 resident, stage1 staged in regs
    LDG_STAGE(0);
    STS_STAGE(0);
    LDG_STAGE(32);
    __syncthreads();

    for (int ck = 0; ck < NC; ck++) {
        // park next stage (regs -> smem), start load of stage+2
        if (ck + 1 < NC) STS_STAGE((ck + 1) % NSTG);
        if (ck + 2 < NC) LDG_STAGE((ck + 2) * 32);

        // ---- compute on stage ck ----
        {
            char* AS = SBUF + (ck % NSTG) * STAGE;
            char* BS = AS + 16384;

            float bh[4][8], bl[4][8];
#pragma unroll
            for (int nt = 0; nt < 4; nt++) {
                int row = wn * 32 + nt * 8 + (lane >> 2);
                uint32_t sw = (uint32_t)((row & 7) << 4);
                uint32_t o0 = (uint32_t)((lane & 3) * 32) ^ sw;
                uint32_t o1 = (uint32_t)((lane & 3) * 32 + 16) ^ sw;
                float4 q0 = *(const float4*)(BS + row * ROWB + o0);
                float4 q1 = *(const float4*)(BS + row * ROWB + o1);
                const float* q = (const float*)&q0;
#pragma unroll
                for (int z = 0; z < 8; z++) {
                    float x = (z < 4) ? q[z] : ((const float*)&q1)[z - 4];
                    if (SPLIT) {
                        float h = __uint_as_float(fu(x) & 0xFFFFE000u);
                        bh[nt][z] = h; bl[nt][z] = x - h;
                    } else {
                        bh[nt][z] = x;
                    }
                }
            }
#pragma unroll
            for (int mt = 0; mt < 4; mt++) {
                float ah[16], al[16];
#pragma unroll
                for (int rr = 0; rr < 2; rr++) {
                    int row = wm * 64 + mt * 16 + (lane >> 2) + rr * 8;
                    uint32_t sw = (uint32_t)((row & 7) << 4);
                    uint32_t o0 = (uint32_t)((lane & 3) * 32) ^ sw;
                    uint32_t o1 = (uint32_t)((lane & 3) * 32 + 16) ^ sw;
                    float4 q0 = *(const float4*)(AS + row * ROWB + o0);
                    float4 q1 = *(const float4*)(AS + row * ROWB + o1);
#pragma unroll
                    for (int z = 0; z < 8; z++) {
                        float x = (z < 4) ? ((const float*)&q0)[z]
                                          : ((const float*)&q1)[z - 4];
                        if (SPLIT) {
                            float h = __uint_as_float(fu(x) & 0xFFFFE000u);
                            ah[rr * 8 + z] = h; al[rr * 8 + z] = x - h;
                        } else {
                            ah[rr * 8 + z] = x;
                        }
                    }
                }
#pragma unroll
                for (int j = 0; j < 4; j++) {
                    const int q = j >> 1, e = (j & 1) * 2;
                    uint32_t aH0 = fu(ah[q * 4 + e]);
                    uint32_t aH1 = fu(ah[8 + q * 4 + e]);
                    uint32_t aH2 = fu(ah[q * 4 + e + 1]);
                    uint32_t aH3 = fu(ah[8 + q * 4 + e + 1]);
                    uint32_t aL0 = 0, aL1 = 0, aL2 = 0, aL3 = 0;
                    if (SPLIT) {
                        aL0 = fu(al[q * 4 + e]);
                        aL1 = fu(al[8 + q * 4 + e]);
                        aL2 = fu(al[q * 4 + e + 1]);
                        aL3 = fu(al[8 + q * 4 + e + 1]);
                    }
#pragma unroll
                    for (int nt = 0; nt < 4; nt++) {
                        uint32_t bH0 = fu(bh[nt][q * 4 + e]);
                        uint32_t bH1 = fu(bh[nt][q * 4 + e + 1]);
                        mma8(acc[mt][nt], aH0, aH1, aH2, aH3, bH0, bH1);
                        if (SPLIT) {
                            uint32_t bL0 = fu(bl[nt][q * 4 + e]);
                            uint32_t bL1 = fu(bl[nt][q * 4 + e + 1]);
                            mma8(acc[mt][nt], aL0, aL1, aL2, aL3, bH0, bH1);
                            mma8(acc[mt][nt], aH0, aH1, aH2, aH3, bL0, bL1);
                        }
                    }
                }
            }
        }
        __syncthreads();
    }

    // ---- epilogue ----
#pragma unroll
    for (int mt = 0; mt < 4; mt++) {
        size_t m0 = (size_t)blockIdx.y * 128 + wm * 64 + mt * 16 + (lane >> 2);
#pragma unroll
        for (int nt = 0; nt < 4; nt++) {
            int cl = wn * 32 + nt * 8 + (lane & 3) * 2;
            int col = n0 + cl;
            float v0 = acc[mt][nt][0] * alpha, v1 = acc[mt][nt][1] * alpha;
            float v2 = acc[mt][nt][2] * alpha, v3 = acc[mt][nt][3] * alpha;
            if (bias) {
                float b0 = sbias[cl], b1 = sbias[cl + 1];
                v0 += b0; v1 += b1; v2 += b0; v3 += b1;
            }
            size_t i0 = m0 * N + col, i1 = (m0 + 8) * N + col;
            if (Rg) {
                v0 += Rg[i0]; v1 += Rg[i0 + 1];
                v2 += Rg[i1]; v3 += Rg[i1 + 1];
            }
            float2 w0; w0.x = v0; w0.y = v1;
            float2 w1; w1.x = v2; w1.y = v3;
            *(float2*)(Cg + i0) = w0;
            *(float2*)(Cg + i1) = w1;
        }
    }
#undef LDG_STAGE
#undef STS_STAGE
}

// ---------------------------------------------------------------------------
__device__ __forceinline__ float fexp(float x) {
    float t = fmaxf(x * 1.4426950408889634f, -126.f);
    float n = rintf(t);
    float f = t - n;
    float p = 0.0013333558f;
    p = fmaf(p, f, 0.0096181291f);
    p = fmaf(p, f, 0.0555041087f);
    p = fmaf(p, f, 0.2402265069f);
    p = fmaf(p, f, 0.6931471806f);
    p = fmaf(p, f, 1.0f);
    return p * __int_as_float(((int)n + 127) << 23);
}

__global__ void __launch_bounds__(256) softmax_k(float* __restrict__ logits) {
    float* p = logits + (size_t)blockIdx.x * Ss;
    const int tid = threadIdx.x;
    float v[8];
#pragma unroll
    for (int i = 0; i < 8; i++) v[i] = p[tid + 256 * i];
    float m = v[0];
#pragma unroll
    for (int i = 1; i < 8; i++) m = fmaxf(m, v[i]);
#pragma unroll
    for (int o = 16; o; o >>= 1) m = fmaxf(m, __shfl_xor_sync(0xffffffffu, m, o));
    __shared__ float rmax[8], rsum[8];
    if ((tid & 31) == 0) rmax[tid >> 5] = m;
    __syncthreads();
#pragma unroll
    for (int i = 0; i < 8; i++) m = fmaxf(m, rmax[i]);
    float s = 0.f;
#pragma unroll
    for (int i = 0; i < 8; i++) { v[i] = fexp(v[i] - m); s += v[i]; }
#pragma unroll
    for (int o = 16; o; o >>= 1) s += __shfl_xor_sync(0xffffffffu, s, o);
    if ((tid & 31) == 0) rsum[tid >> 5] = s;
    __syncthreads();
    s = 0.f;
#pragma unroll
    for (int i = 0; i < 8; i++) s += rsum[i];
    float inv = 1.f / s;
#pragma unroll
    for (int i = 0; i < 8; i++) p[tid + 256 * i] = v[i] * inv;
}

__global__ void __launch_bounds__(256) ln_relu_k(
    float* __restrict__ h, const float* __restrict__ g, const float* __restrict__ b)
{
    float* p = h + (size_t)blockIdx.x * Cc;
    const int tid = threadIdx.x;
    float v[4];
    float s = 0.f, ss = 0.f;
#pragma unroll
    for (int i = 0; i < 4; i++) {
        v[i] = p[tid + 256 * i];
        s += v[i];
        ss += v[i] * v[i];
    }
#pragma unroll
    for (int o = 16; o; o >>= 1) {
        s  += __shfl_xor_sync(0xffffffffu, s, o);
        ss += __shfl_xor_sync(0xffffffffu, ss, o);
    }
    __shared__ float r1[8], r2[8];
    if ((tid & 31) == 0) { r1[tid >> 5] = s; r2[tid >> 5] = ss; }
    __syncthreads();
    s = 0.f; ss = 0.f;
#pragma unroll
    for (int i = 0; i < 8; i++) { s += r1[i]; ss += r2[i]; }
    float mean = s * (1.f / Cc);
    float var  = ss * (1.f / Cc) - mean * mean;
    float inv  = rsqrtf(var + 1e-5f);
#pragma unroll
    for (int i = 0; i < 4; i++) {
        int c = tid + 256 * i;
        float y = (v[i] - mean) * inv * g[c] + b[c];
        p[c] = fmaxf(y, 0.f);
    }
}

// ---------------------------------------------------------------------------
extern "C" void kernel_launch(void* const* d_in, const int* in_sizes, int n_in,
                              void* d_out, int out_size)
{
    (void)in_sizes; (void)n_in; (void)out_size;
    const float* x       = (const float*)d_in[0];
    const float* lfb     = (const float*)d_in[1];
    const float* theta_w = (const float*)d_in[2];
    const float* theta_b = (const float*)d_in[3];
    const float* phi_w   = (const float*)d_in[4];
    const float* phi_b   = (const float*)d_in[5];
    const float* gi_w    = (const float*)d_in[6];
    const float* gi_b    = (const float*)d_in[7];
    const float* ln_g    = (const float*)d_in[8];
    const float* ln_b    = (const float*)d_in[9];
    const float* fc_w    = (const float*)d_in[10];
    const float* fc_b    = (const float*)d_in[11];
    float* out = (float*)d_out;

    float *theta, *phi, *gi, *logits, *att;
    cudaGetSymbolAddress((void**)&theta,  g_theta);
    cudaGetSymbolAddress((void**)&phi,    g_phi);
    cudaGetSymbolAddress((void**)&gi,     g_gi);
    cudaGetSymbolAddress((void**)&logits, g_logits);
    cudaGetSymbolAddress((void**)&att,    g_att);

    cudaFuncSetAttribute(gemm_mma<true,  false>,
        cudaFuncAttributeMaxDynamicSharedMemorySize, SMEM_ALL);
    cudaFuncSetAttribute(gemm_mma<false, false>,
        cudaFuncAttributeMaxDynamicSharedMemorySize, SMEM_ALL);
    cudaFuncSetAttribute(gemm_mma<false, true>,
        cudaFuncAttributeMaxDynamicSharedMemorySize, SMEM_ALL);

    dim3 blk(256);
    const float scale = 32.0f;   // sqrt(C)

    // theta = x @ theta_w^T + theta_b               [8192,1024]  (split)
    gemm_mma<true, false><<<dim3(8, 64, 1), blk, SMEM_ALL>>>(
        x, theta_w, theta_b, nullptr, theta, Cc, Cc, 0, 1.f, 0, 0, 0);
    // phi = lfb @ phi_w^T + phi_b                   [16384,1024] (split)
    gemm_mma<true, false><<<dim3(8, 128, 1), blk, SMEM_ALL>>>(
        lfb, phi_w, phi_b, nullptr, phi, Cc, Cc, 0, 1.f, 0, 0, 0);
    // gi = lfb @ gi_w^T + gi_b                      [16384,1024] (single)
    gemm_mma<false, false><<<dim3(8, 128, 1), blk, SMEM_ALL>>>(
        lfb, gi_w, gi_b, nullptr, gi, Cc, Cc, 0, 1.f, 0, 0, 0);
    // logits[b] = 32 * theta[b] @ phi[b]^T          [1024,2048]x8 (split)
    gemm_mma<true, false><<<dim3(16, 8, Bv), blk, SMEM_ALL>>>(
        theta, phi, nullptr, nullptr, logits, Ss, Cc, 0, scale,
        (size_t)Tt * Cc, (size_t)Ss * Cc, (size_t)Tt * Ss);
    softmax_k<<<Bv * Tt, blk>>>(logits);
    // att[b] = attn[b] @ gi[b]   (gi is [K=2048, N=1024] -> TB, single)
    gemm_mma<false, true><<<dim3(8, 8, Bv), blk, SMEM_ALL>>>(
        logits, gi, nullptr, nullptr, att, Cc, Ss, Cc, 1.f,
        (size_t)Tt * Ss, (size_t)Ss * Cc, (size_t)Tt * Cc);
    ln_relu_k<<<Bv * Tt, blk>>>(att, ln_g, ln_b);
    // out = relu(LN(att)) @ fc_w^T + fc_b + x       [8192,1024]  (single)
    gemm_mma<false, false><<<dim3(8, 64, 1), blk, SMEM_ALL>>>(
        att, fc_w, fc_b, x, out, Cc, Cc, 0, 1.f, 0, 0, 0);
}

// round 9
// speedup vs baseline: 2.0730x; 1.1798x over previous
#include <cuda_runtime.h>
#include <math.h>
#include <stdint.h>

// ---------------------------------------------------------------------------
// _NLBlock on GB300, legacy mma.sync tf32 (compute_103-safe).
// R7: R6 design (cp.async 3-stage pipeline, natural+XOR16 smem layout,
// split/round at fragment use, transposed gi so all GEMMs are NT) with the
// shared-space addressing bug fixed: fragment loads now use ld.shared.f32
// on cvta'd u32 addresses instead of dereferencing them as generic pointers.
// ---------------------------------------------------------------------------

#define Bv 8
#define Tt 1024
#define Ss 2048
#define Cc 1024

__device__ float g_theta [Bv * Tt * Cc];
__device__ float g_phi   [Bv * Ss * Cc];
__device__ float g_giT   [Bv * Cc * Ss];   // transposed: [b][c][s]
__device__ float g_logits[Bv * Tt * Ss];
__device__ float g_att   [Bv * Tt * Cc];

__device__ __forceinline__ uint32_t fu(float f) { return __float_as_uint(f); }

__device__ __forceinline__ float rtf32(float x) {
    uint32_t u;
    asm("cvt.rna.tf32.f32 %0, %1;" : "=r"(u) : "f"(x));
    return __uint_as_float(u);
}

__device__ __forceinline__ uint32_t s2u(const void* p) {
    uint32_t a;
    asm("{ .reg .u64 t; cvta.to.shared.u64 t, %1; cvt.u32.u64 %0, t; }"
        : "=r"(a) : "l"(p));
    return a;
}

__device__ __forceinline__ float lds32(uint32_t a) {
    float v;
    asm volatile("ld.shared.f32 %0, [%1];" : "=f"(v) : "r"(a));
    return v;
}

__device__ __forceinline__ void cpa16(uint32_t s, const void* g) {
    asm volatile("cp.async.cg.shared.global [%0], [%1], 16;"
                 :: "r"(s), "l"(g) : "memory");
}
#define CP_COMMIT() asm volatile("cp.async.commit_group;" ::: "memory")
#define CP_WAIT(n)  asm volatile("cp.async.wait_group %0;" :: "n"(n) : "memory")

__device__ __forceinline__ void mma8(float* d, uint32_t a0, uint32_t a1,
                                     uint32_t a2, uint32_t a3,
                                     uint32_t b0, uint32_t b1) {
    asm("mma.sync.aligned.m16n8k8.row.col.f32.tf32.tf32.f32 "
        "{%0,%1,%2,%3}, {%4,%5,%6,%7}, {%8,%9}, {%0,%1,%2,%3};"
        : "+f"(d[0]), "+f"(d[1]), "+f"(d[2]), "+f"(d[3])
        : "r"(a0), "r"(a1), "r"(a2), "r"(a3), "r"(b0), "r"(b1));
}

// smem tile: 128 rows x 128B (32 fp32, k natural order), 16B-block XOR swizzle:
//   byte(row,k) = row*128 + ((k*4) ^ ((row&7)<<4))
constexpr int STAGE = 32768;                    // A 16KB + B 16KB
constexpr int NSTG  = 3;
constexpr int SMEM_ALL = 1024 + NSTG * STAGE;   // 99328 (>= 1024+67584 for tb)

// ---------------------------------------------------------------------------
// NT GEMM, CTA tile 128x128x32, 256 thr (8 warps: 2M x 4N, 64x32 per warp)
//   SPLIT: hi/lo 3xTF32 at fragment use   TRANS: write C transposed [n][m]
//   C = alpha * A@B^T (+bias[n]) (+res)
// ---------------------------------------------------------------------------
template <bool SPLIT, bool TRANS>
__global__ void __launch_bounds__(256, 1) gemm_cp(
    const float* __restrict__ A, const float* __restrict__ B,
    const float* __restrict__ bias, const float* __restrict__ res,
    float* __restrict__ C,
    int N, int K, float alpha,
    size_t sA, size_t sB, size_t sC)
{
    extern __shared__ char sm[];
    const uint32_t sb = s2u(sm);
    const int tid  = threadIdx.x;
    const int lane = tid & 31;
    const int wid  = tid >> 5;
    const int wm   = wid >> 2;
    const int wn   = wid & 3;
    const int n0   = blockIdx.x * 128;

    const float* Ag = A + blockIdx.z * sA + (size_t)blockIdx.y * 128 * K;
    const float* Bg = B + blockIdx.z * sB + (size_t)n0 * K;
    float* Cg = C + blockIdx.z * sC;
    const float* Rg = res ? res + blockIdx.z * sC : nullptr;

    float* sbias = (float*)sm;                  // 512 B
    if (bias && tid < 128) sbias[tid] = bias[n0 + tid];

    // per-thread cp.async tasks: 1024 16B-copies per tile, 4 per thread
    size_t   goff[4];
    uint32_t soff[4];
#pragma unroll
    for (int i = 0; i < 4; i++) {
        int v = i * 256 + tid;
        int r = v >> 3, c4 = v & 7;
        goff[i] = (size_t)r * K + c4 * 4;
        soff[i] = (uint32_t)(r * 128 + ((c4 * 16) ^ ((r & 7) << 4)));
    }
    const uint32_t stg[3] = {sb + 1024, sb + 1024 + STAGE, sb + 1024 + 2 * STAGE};

#define ISSUE(CK)                                                             \
    {                                                                         \
        uint32_t st = stg[(CK) % 3];                                          \
        int k0 = (CK) * 32;                                                   \
        _Pragma("unroll")                                                     \
        for (int i = 0; i < 4; i++)                                           \
            cpa16(st + soff[i], Ag + goff[i] + k0);                           \
        _Pragma("unroll")                                                     \
        for (int i = 0; i < 4; i++)                                           \
            cpa16(st + 16384 + soff[i], Bg + goff[i] + k0);                   \
        CP_COMMIT();                                                          \
    }

    float acc[4][4][4];
#pragma unroll
    for (int mt = 0; mt < 4; mt++)
#pragma unroll
        for (int nt = 0; nt < 4; nt++)
#pragma unroll
            for (int e = 0; e < 4; e++) acc[mt][nt][e] = 0.f;

    const int NC = K / 32;
    ISSUE(0);
    ISSUE(1);

    const uint32_t cB = (uint32_t)(lane & 3) * 4;   // byte offset of k-lane
    const int      rq = lane >> 2;

    for (int ck = 0; ck < NC; ck++) {
        if (ck + 1 < NC) { CP_WAIT(1); } else { CP_WAIT(0); }
        __syncthreads();
        if (ck + 2 < NC) ISSUE(ck + 2);

        const uint32_t AS = stg[ck % 3];
        const uint32_t BS = AS + 16384;

        // ---- B fragments: 4 nt rows ----
        float bh[4][4][2], bl[4][4][2];
#pragma unroll
        for (int nt = 0; nt < 4; nt++) {
            int row = wn * 32 + nt * 8 + rq;
            uint32_t rb = BS + row * 128;
            uint32_t sw = (uint32_t)((row & 7) << 4);
#pragma unroll
            for (int j = 0; j < 4; j++) {
#pragma unroll
                for (int p = 0; p < 2; p++) {
                    float x = lds32(rb + (((uint32_t)(j * 32 + p * 16) + cB) ^ sw));
                    if (SPLIT) {
                        float h = __uint_as_float(fu(x) & 0xFFFFE000u);
                        bh[nt][j][p] = h; bl[nt][j][p] = x - h;
                    } else {
                        bh[nt][j][p] = rtf32(x);
                    }
                }
            }
        }
        // ---- A fragments per mt, then MMAs ----
#pragma unroll
        for (int mt = 0; mt < 4; mt++) {
            float ah[2][4][2], al[2][4][2];
#pragma unroll
            for (int rr = 0; rr < 2; rr++) {
                int row = wm * 64 + mt * 16 + rq + rr * 8;
                uint32_t rb = AS + row * 128;
                uint32_t sw = (uint32_t)((row & 7) << 4);
#pragma unroll
                for (int j = 0; j < 4; j++) {
#pragma unroll
                    for (int p = 0; p < 2; p++) {
                        float x = lds32(rb + (((uint32_t)(j * 32 + p * 16) + cB) ^ sw));
                        if (SPLIT) {
                            float h = __uint_as_float(fu(x) & 0xFFFFE000u);
                            ah[rr][j][p] = h; al[rr][j][p] = x - h;
                        } else {
                            ah[rr][j][p] = rtf32(x);
                        }
                    }
                }
            }
#pragma unroll
            for (int j = 0; j < 4; j++) {
                uint32_t aH0 = fu(ah[0][j][0]), aH1 = fu(ah[1][j][0]);
                uint32_t aH2 = fu(ah[0][j][1]), aH3 = fu(ah[1][j][1]);
                uint32_t aL0 = 0, aL1 = 0, aL2 = 0, aL3 = 0;
                if (SPLIT) {
                    aL0 = fu(al[0][j][0]); aL1 = fu(al[1][j][0]);
                    aL2 = fu(al[0][j][1]); aL3 = fu(al[1][j][1]);
                }
#pragma unroll
                for (int nt = 0; nt < 4; nt++) {
                    uint32_t bH0 = fu(bh[nt][j][0]), bH1 = fu(bh[nt][j][1]);
                    mma8(acc[mt][nt], aH0, aH1, aH2, aH3, bH0, bH1);
                    if (SPLIT) {
                        uint32_t bL0 = fu(bl[nt][j][0]);
                        uint32_t bL1 = fu(bl[nt][j][1]);
                        mma8(acc[mt][nt], aL0, aL1, aL2, aL3, bH0, bH1);
                        mma8(acc[mt][nt], aH0, aH1, aH2, aH3, bL0, bL1);
                    }
                }
            }
        }
    }

    if (!TRANS) {
        // ---- direct epilogue ----
#pragma unroll
        for (int mt = 0; mt < 4; mt++) {
            size_t m0 = (size_t)blockIdx.y * 128 + wm * 64 + mt * 16 + rq;
#pragma unroll
            for (int nt = 0; nt < 4; nt++) {
                int cl = wn * 32 + nt * 8 + (lane & 3) * 2;
                int col = n0 + cl;
                float v0 = acc[mt][nt][0] * alpha, v1 = acc[mt][nt][1] * alpha;
                float v2 = acc[mt][nt][2] * alpha, v3 = acc[mt][nt][3] * alpha;
                if (bias) {
                    float b0 = sbias[cl], b1 = sbias[cl + 1];
                    v0 += b0; v1 += b1; v2 += b0; v3 += b1;
                }
                size_t i0 = m0 * N + col, i1 = (m0 + 8) * N + col;
                if (Rg) {
                    v0 += Rg[i0]; v1 += Rg[i0 + 1];
                    v2 += Rg[i1]; v3 += Rg[i1 + 1];
                }
                float2 w0; w0.x = v0; w0.y = v1;
                float2 w1; w1.x = v2; w1.y = v3;
                *(float2*)(Cg + i0) = w0;
                *(float2*)(Cg + i1) = w1;
            }
        }
    } else {
        // ---- transposed epilogue via smem (128 cols x 132-padded rows) ----
        __syncthreads();                       // stages dead, reuse as buffer
        float* tb = (float*)(sm + 1024);
#pragma unroll
        for (int mt = 0; mt < 4; mt++) {
            int ml = wm * 64 + mt * 16 + rq;
#pragma unroll
            for (int nt = 0; nt < 4; nt++) {
                int cl = wn * 32 + nt * 8 + (lane & 3) * 2;
                float v0 = acc[mt][nt][0] * alpha, v1 = acc[mt][nt][1] * alpha;
                float v2 = acc[mt][nt][2] * alpha, v3 = acc[mt][nt][3] * alpha;
                if (bias) {
                    float b0 = sbias[cl], b1 = sbias[cl + 1];
                    v0 += b0; v1 += b1; v2 += b0; v3 += b1;
                }
                tb[cl * 132 + ml]           = v0;
                tb[(cl + 1) * 132 + ml]     = v1;
                tb[cl * 132 + ml + 8]       = v2;
                tb[(cl + 1) * 132 + ml + 8] = v3;
            }
        }
        __syncthreads();
        // each warp writes 16 output rows (n = channel), coalesced STG.128
        size_t mg_base = (size_t)blockIdx.y * 128 + lane * 4;
        size_t b  = mg_base >> 11;             // 2048 rows per batch
        size_t s  = mg_base & 2047;
        float* Ct = C + b * (size_t)Cc * Ss + s;
#pragma unroll
        for (int rr = 0; rr < 16; rr++) {
            int n = wid * 16 + rr;
            float4 v = *(const float4*)(tb + n * 132 + lane * 4);
            *(float4*)(Ct + (size_t)(n0 + n) * Ss) = v;
        }
    }
#undef ISSUE
}

// ---------------------------------------------------------------------------
__device__ __forceinline__ float fexp(float x) {
    float t = fmaxf(x * 1.4426950408889634f, -126.f);
    float n = rintf(t);
    float f = t - n;
    float p = 0.0013333558f;
    p = fmaf(p, f, 0.0096181291f);
    p = fmaf(p, f, 0.0555041087f);
    p = fmaf(p, f, 0.2402265069f);
    p = fmaf(p, f, 0.6931471806f);
    p = fmaf(p, f, 1.0f);
    return p * __int_as_float(((int)n + 127) << 23);
}

__global__ void __launch_bounds__(256) softmax_k(float* __restrict__ logits) {
    float* p = logits + (size_t)blockIdx.x * Ss;
    const int tid = threadIdx.x;
    float v[8];
#pragma unroll
    for (int i = 0; i < 8; i++) v[i] = p[tid + 256 * i];
    float m = v[0];
#pragma unroll
    for (int i = 1; i < 8; i++) m = fmaxf(m, v[i]);
#pragma unroll
    for (int o = 16; o; o >>= 1) m = fmaxf(m, __shfl_xor_sync(0xffffffffu, m, o));
    __shared__ float rmax[8], rsum[8];
    if ((tid & 31) == 0) rmax[tid >> 5] = m;
    __syncthreads();
#pragma unroll
    for (int i = 0; i < 8; i++) m = fmaxf(m, rmax[i]);
    float s = 0.f;
#pragma unroll
    for (int i = 0; i < 8; i++) { v[i] = fexp(v[i] - m); s += v[i]; }
#pragma unroll
    for (int o = 16; o; o >>= 1) s += __shfl_xor_sync(0xffffffffu, s, o);
    if ((tid & 31) == 0) rsum[tid >> 5] = s;
    __syncthreads();
    s = 0.f;
#pragma unroll
    for (int i = 0; i < 8; i++) s += rsum[i];
    float inv = 1.f / s;
#pragma unroll
    for (int i = 0; i < 8; i++) p[tid + 256 * i] = v[i] * inv;
}

__global__ void __launch_bounds__(256) ln_relu_k(
    float* __restrict__ h, const float* __restrict__ g, const float* __restrict__ b)
{
    float* p = h + (size_t)blockIdx.x * Cc;
    const int tid = threadIdx.x;
    float v[4];
    float s = 0.f, ss = 0.f;
#pragma unroll
    for (int i = 0; i < 4; i++) {
        v[i] = p[tid + 256 * i];
        s += v[i];
        ss += v[i] * v[i];
    }
#pragma unroll
    for (int o = 16; o; o >>= 1) {
        s  += __shfl_xor_sync(0xffffffffu, s, o);
        ss += __shfl_xor_sync(0xffffffffu, ss, o);
    }
    __shared__ float r1[8], r2[8];
    if ((tid & 31) == 0) { r1[tid >> 5] = s; r2[tid >> 5] = ss; }
    __syncthreads();
    s = 0.f; ss = 0.f;
#pragma unroll
    for (int i = 0; i < 8; i++) { s += r1[i]; ss += r2[i]; }
    float mean = s * (1.f / Cc);
    float var  = ss * (1.f / Cc) - mean * mean;
    float inv  = rsqrtf(var + 1e-5f);
#pragma unroll
    for (int i = 0; i < 4; i++) {
        int c = tid + 256 * i;
        float y = (v[i] - mean) * inv * g[c] + b[c];
        p[c] = fmaxf(y, 0.f);
    }
}

// ---------------------------------------------------------------------------
extern "C" void kernel_launch(void* const* d_in, const int* in_sizes, int n_in,
                              void* d_out, int out_size)
{
    (void)in_sizes; (void)n_in; (void)out_size;
    const float* x       = (const float*)d_in[0];
    const float* lfb     = (const float*)d_in[1];
    const float* theta_w = (const float*)d_in[2];
    const float* theta_b = (const float*)d_in[3];
    const float* phi_w   = (const float*)d_in[4];
    const float* phi_b   = (const float*)d_in[5];
    const float* gi_w    = (const float*)d_in[6];
    const float* gi_b    = (const float*)d_in[7];
    const float* ln_g    = (const float*)d_in[8];
    const float* ln_b    = (const float*)d_in[9];
    const float* fc_w    = (const float*)d_in[10];
    const float* fc_b    = (const float*)d_in[11];
    float* out = (float*)d_out;

    float *theta, *phi, *giT, *logits, *att;
    cudaGetSymbolAddress((void**)&theta,  g_theta);
    cudaGetSymbolAddress((void**)&phi,    g_phi);
    cudaGetSymbolAddress((void**)&giT,    g_giT);
    cudaGetSymbolAddress((void**)&logits, g_logits);
    cudaGetSymbolAddress((void**)&att,    g_att);

    cudaFuncSetAttribute(gemm_cp<true,  false>,
        cudaFuncAttributeMaxDynamicSharedMemorySize, SMEM_ALL);
    cudaFuncSetAttribute(gemm_cp<false, false>,
        cudaFuncAttributeMaxDynamicSharedMemorySize, SMEM_ALL);
    cudaFuncSetAttribute(gemm_cp<false, true>,
        cudaFuncAttributeMaxDynamicSharedMemorySize, SMEM_ALL);

    dim3 blk(256);
    const float scale = 32.0f;   // sqrt(C)

    // theta = x @ theta_w^T + theta_b                [8192,1024]  (split)
    gemm_cp<true, false><<<dim3(8, 64, 1), blk, SMEM_ALL>>>(
        x, theta_w, theta_b, nullptr, theta, Cc, Cc, 1.f, 0, 0, 0);
    // phi = lfb @ phi_w^T + phi_b                    [16384,1024] (split)
    gemm_cp<true, false><<<dim3(8, 128, 1), blk, SMEM_ALL>>>(
        lfb, phi_w, phi_b, nullptr, phi, Cc, Cc, 1.f, 0, 0, 0);
    // giT[b][c][s] = (lfb @ gi_w^T + gi_b)^T         (single, transposed out)
    gemm_cp<false, true><<<dim3(8, 128, 1), blk, SMEM_ALL>>>(
        lfb, gi_w, gi_b, nullptr, giT, Cc, Cc, 1.f, 0, 0, 0);
    // logits[b] = 32 * theta[b] @ phi[b]^T           [1024,2048]x8 (split)
    gemm_cp<true, false><<<dim3(16, 8, Bv), blk, SMEM_ALL>>>(
        theta, phi, nullptr, nullptr, logits, Ss, Cc, scale,
        (size_t)Tt * Cc, (size_t)Ss * Cc, (size_t)Tt * Ss);
    softmax_k<<<Bv * Tt, blk>>>(logits);
    // att[b] = attn[b] @ giT[b]^T                    [1024,1024]x8 (single NT)
    gemm_cp<false, false><<<dim3(8, 8, Bv), blk, SMEM_ALL>>>(
        logits, giT, nullptr, nullptr, att, Cc, Ss, 1.f,
        (size_t)Tt * Ss, (size_t)Cc * Ss, (size_t)Tt * Cc);
    ln_relu_k<<<Bv * Tt, blk>>>(att, ln_g, ln_b);
    // out = relu(LN(att)) @ fc_w^T + fc_b + x        [8192,1024]  (single)
    gemm_cp<false, false><<<dim3(8, 64, 1), blk, SMEM_ALL>>>(
        att, fc_w, fc_b, x, out, Cc, Cc, 1.f, 0, 0, 0);
}

// round 10
// speedup vs baseline: 2.3064x; 1.1126x over previous
#include <cuda_runtime.h>
#include <math.h>
#include <stdint.h>

// ---------------------------------------------------------------------------
// _NLBlock on GB300, legacy mma.sync tf32 (compute_103-safe).
// R8: 2 CTAs/SM (launch_bounds 256,2; regs<=128 via j-outer fragment loop),
// cp.async 3-stage pipeline, XOR16 smem layout, split-at-use 3xTF32,
// transposed gi so all GEMMs are NT.
// ---------------------------------------------------------------------------

#define Bv 8
#define Tt 1024
#define Ss 2048
#define Cc 1024

__device__ float g_theta [Bv * Tt * Cc];
__device__ float g_phi   [Bv * Ss * Cc];
__device__ float g_giT   [Bv * Cc * Ss];   // transposed: [b][c][s]
__device__ float g_logits[Bv * Tt * Ss];
__device__ float g_att   [Bv * Tt * Cc];

__device__ __forceinline__ uint32_t fu(float f) { return __float_as_uint(f); }

__device__ __forceinline__ float rtf32(float x) {
    uint32_t u;
    asm("cvt.rna.tf32.f32 %0, %1;" : "=r"(u) : "f"(x));
    return __uint_as_float(u);
}

__device__ __forceinline__ uint32_t s2u(const void* p) {
    uint32_t a;
    asm("{ .reg .u64 t; cvta.to.shared.u64 t, %1; cvt.u32.u64 %0, t; }"
        : "=r"(a) : "l"(p));
    return a;
}

__device__ __forceinline__ float lds32(uint32_t a) {
    float v;
    asm volatile("ld.shared.f32 %0, [%1];" : "=f"(v) : "r"(a));
    return v;
}

__device__ __forceinline__ void cpa16(uint32_t s, const void* g) {
    asm volatile("cp.async.cg.shared.global [%0], [%1], 16;"
                 :: "r"(s), "l"(g) : "memory");
}
#define CP_COMMIT() asm volatile("cp.async.commit_group;" ::: "memory")
#define CP_WAIT(n)  asm volatile("cp.async.wait_group %0;" :: "n"(n) : "memory")

__device__ __forceinline__ void mma8(float* d, uint32_t a0, uint32_t a1,
                                     uint32_t a2, uint32_t a3,
                                     uint32_t b0, uint32_t b1) {
    asm("mma.sync.aligned.m16n8k8.row.col.f32.tf32.tf32.f32 "
        "{%0,%1,%2,%3}, {%4,%5,%6,%7}, {%8,%9}, {%0,%1,%2,%3};"
        : "+f"(d[0]), "+f"(d[1]), "+f"(d[2]), "+f"(d[3])
        : "r"(a0), "r"(a1), "r"(a2), "r"(a3), "r"(b0), "r"(b1));
}

// smem tile: 128 rows x 128B (32 fp32, k natural order), 16B-block XOR swizzle:
//   byte(row,k) = row*128 + ((k*4) ^ ((row&7)<<4))
constexpr int STAGE = 32768;                    // A 16KB + B 16KB
constexpr int NSTG  = 3;
constexpr int SMEM_ALL = 1024 + NSTG * STAGE;   // 99328; x2 CTAs = 194KB/SM

// ---------------------------------------------------------------------------
// NT GEMM, CTA tile 128x128x32, 256 thr (8 warps: 2M x 4N, 64x32 per warp)
//   SPLIT: hi/lo 3xTF32 at fragment use   TRANS: write C transposed [n][m]
//   C = alpha * A@B^T (+bias[n]) (+res)
// ---------------------------------------------------------------------------
template <bool SPLIT, bool TRANS>
__global__ void __launch_bounds__(256, 2) gemm_cp(
    const float* __restrict__ A, const float* __restrict__ B,
    const float* __restrict__ bias, const float* __restrict__ res,
    float* __restrict__ C,
    int N, int K, float alpha,
    size_t sA, size_t sB, size_t sC)
{
    extern __shared__ char sm[];
    const uint32_t sb = s2u(sm);
    const int tid  = threadIdx.x;
    const int lane = tid & 31;
    const int wid  = tid >> 5;
    const int wm   = wid >> 2;
    const int wn   = wid & 3;
    const int n0   = blockIdx.x * 128;

    const float* Ag = A + blockIdx.z * sA + (size_t)blockIdx.y * 128 * K;
    const float* Bg = B + blockIdx.z * sB + (size_t)n0 * K;
    float* Cg = C + blockIdx.z * sC;
    const float* Rg = res ? res + blockIdx.z * sC : nullptr;

    float* sbias = (float*)sm;                  // 512 B
    if (bias && tid < 128) sbias[tid] = bias[n0 + tid];

    // per-thread cp.async tasks: 1024 16B-copies per tile, 4 per thread
    size_t   goff[4];
    uint32_t soff[4];
#pragma unroll
    for (int i = 0; i < 4; i++) {
        int v = i * 256 + tid;
        int r = v >> 3, c4 = v & 7;
        goff[i] = (size_t)r * K + c4 * 4;
        soff[i] = (uint32_t)(r * 128 + ((c4 * 16) ^ ((r & 7) << 4)));
    }
    const uint32_t stg0 = sb + 1024;

#define ISSUE(CK)                                                             \
    {                                                                         \
        uint32_t st = stg0 + ((CK) % NSTG) * STAGE;                           \
        int k0 = (CK) * 32;                                                   \
        _Pragma("unroll")                                                     \
        for (int i = 0; i < 4; i++)                                           \
            cpa16(st + soff[i], Ag + goff[i] + k0);                           \
        _Pragma("unroll")                                                     \
        for (int i = 0; i < 4; i++)                                           \
            cpa16(st + 16384 + soff[i], Bg + goff[i] + k0);                   \
        CP_COMMIT();                                                          \
    }

    float acc[4][4][4];
#pragma unroll
    for (int mt = 0; mt < 4; mt++)
#pragma unroll
        for (int nt = 0; nt < 4; nt++)
#pragma unroll
            for (int e = 0; e < 4; e++) acc[mt][nt][e] = 0.f;

    const int NC = K / 32;
    ISSUE(0);
    ISSUE(1);

    const uint32_t cB = (uint32_t)(lane & 3) * 4;   // k-lane byte offset
    const int      rq = lane >> 2;

    for (int ck = 0; ck < NC; ck++) {
        if (ck + 1 < NC) { CP_WAIT(1); } else { CP_WAIT(0); }
        __syncthreads();
        if (ck + 2 < NC) ISSUE(ck + 2);

        const uint32_t AS = stg0 + (ck % NSTG) * STAGE;
        const uint32_t BS = AS + 16384;

        // j-outer: hold only one k-step of fragments (regs <= 128 for occ 2)
#pragma unroll
        for (int j = 0; j < 4; j++) {
            const uint32_t jb = (uint32_t)(j * 32) + cB;

            // ---- B fragments for this k-step (4 nt rows) ----
            float bh[4][2], bl[4][2];
#pragma unroll
            for (int nt = 0; nt < 4; nt++) {
                int row = wn * 32 + nt * 8 + rq;
                uint32_t rb = BS + row * 128;
                uint32_t sw = (uint32_t)((row & 7) << 4);
#pragma unroll
                for (int p = 0; p < 2; p++) {
                    float x = lds32(rb + ((jb + (uint32_t)(p * 16)) ^ sw));
                    if (SPLIT) {
                        float h = __uint_as_float(fu(x) & 0xFFFFE000u);
                        bh[nt][p] = h; bl[nt][p] = x - h;
                    } else {
                        bh[nt][p] = rtf32(x);
                    }
                }
            }
            // ---- per mt: A fragments then MMAs ----
#pragma unroll
            for (int mt = 0; mt < 4; mt++) {
                float ah[2][2], al[2][2];
#pragma unroll
                for (int rr = 0; rr < 2; rr++) {
                    int row = wm * 64 + mt * 16 + rq + rr * 8;
                    uint32_t rb = AS + row * 128;
                    uint32_t sw = (uint32_t)((row & 7) << 4);
#pragma unroll
                    for (int p = 0; p < 2; p++) {
                        float x = lds32(rb + ((jb + (uint32_t)(p * 16)) ^ sw));
                        if (SPLIT) {
                            float h = __uint_as_float(fu(x) & 0xFFFFE000u);
                            ah[rr][p] = h; al[rr][p] = x - h;
                        } else {
                            ah[rr][p] = rtf32(x);
                        }
                    }
                }
                uint32_t aH0 = fu(ah[0][0]), aH1 = fu(ah[1][0]);
                uint32_t aH2 = fu(ah[0][1]), aH3 = fu(ah[1][1]);
                uint32_t aL0 = 0, aL1 = 0, aL2 = 0, aL3 = 0;
                if (SPLIT) {
                    aL0 = fu(al[0][0]); aL1 = fu(al[1][0]);
                    aL2 = fu(al[0][1]); aL3 = fu(al[1][1]);
                }
#pragma unroll
                for (int nt = 0; nt < 4; nt++) {
                    uint32_t bH0 = fu(bh[nt][0]), bH1 = fu(bh[nt][1]);
                    mma8(acc[mt][nt], aH0, aH1, aH2, aH3, bH0, bH1);
                    if (SPLIT) {
                        uint32_t bL0 = fu(bl[nt][0]);
                        uint32_t bL1 = fu(bl[nt][1]);
                        mma8(acc[mt][nt], aL0, aL1, aL2, aL3, bH0, bH1);
                        mma8(acc[mt][nt], aH0, aH1, aH2, aH3, bL0, bL1);
                    }
                }
            }
        }
    }

    if (!TRANS) {
        // ---- direct epilogue ----
#pragma unroll
        for (int mt = 0; mt < 4; mt++) {
            size_t m0 = (size_t)blockIdx.y * 128 + wm * 64 + mt * 16 + rq;
#pragma unroll
            for (int nt = 0; nt < 4; nt++) {
                int cl = wn * 32 + nt * 8 + (lane & 3) * 2;
                int col = n0 + cl;
                float v0 = acc[mt][nt][0] * alpha, v1 = acc[mt][nt][1] * alpha;
                float v2 = acc[mt][nt][2] * alpha, v3 = acc[mt][nt][3] * alpha;
                if (bias) {
                    float b0 = sbias[cl], b1 = sbias[cl + 1];
                    v0 += b0; v1 += b1; v2 += b0; v3 += b1;
                }
                size_t i0 = m0 * N + col, i1 = (m0 + 8) * N + col;
                if (Rg) {
                    v0 += Rg[i0]; v1 += Rg[i0 + 1];
                    v2 += Rg[i1]; v3 += Rg[i1 + 1];
                }
                float2 w0; w0.x = v0; w0.y = v1;
                float2 w1; w1.x = v2; w1.y = v3;
                *(float2*)(Cg + i0) = w0;
                *(float2*)(Cg + i1) = w1;
            }
        }
    } else {
        // ---- transposed epilogue via smem (128 cols x 132-padded rows) ----
        __syncthreads();                       // stages dead, reuse as buffer
        float* tb = (float*)(sm + 1024);
#pragma unroll
        for (int mt = 0; mt < 4; mt++) {
            int ml = wm * 64 + mt * 16 + rq;
#pragma unroll
            for (int nt = 0; nt < 4; nt++) {
                int cl = wn * 32 + nt * 8 + (lane & 3) * 2;
                float v0 = acc[mt][nt][0] * alpha, v1 = acc[mt][nt][1] * alpha;
                float v2 = acc[mt][nt][2] * alpha, v3 = acc[mt][nt][3] * alpha;
                if (bias) {
                    float b0 = sbias[cl], b1 = sbias[cl + 1];
                    v0 += b0; v1 += b1; v2 += b0; v3 += b1;
                }
                tb[cl * 132 + ml]           = v0;
                tb[(cl + 1) * 132 + ml]     = v1;
                tb[cl * 132 + ml + 8]       = v2;
                tb[(cl + 1) * 132 + ml + 8] = v3;
            }
        }
        __syncthreads();
        // each warp writes 16 output rows (n = channel), coalesced STG.128
        size_t mg_base = (size_t)blockIdx.y * 128 + lane * 4;
        size_t b  = mg_base >> 11;             // 2048 rows per batch
        size_t s  = mg_base & 2047;
        float* Ct = C + b * (size_t)Cc * Ss + s;
#pragma unroll
        for (int rr = 0; rr < 16; rr++) {
            int n = wid * 16 + rr;
            float4 v = *(const float4*)(tb + n * 132 + lane * 4);
            *(float4*)(Ct + (size_t)(n0 + n) * Ss) = v;
        }
    }
#undef ISSUE
}

// ---------------------------------------------------------------------------
__device__ __forceinline__ float fexp(float x) {
    float t = fmaxf(x * 1.4426950408889634f, -126.f);
    float n = rintf(t);
    float f = t - n;
    float p = 0.0013333558f;
    p = fmaf(p, f, 0.0096181291f);
    p = fmaf(p, f, 0.0555041087f);
    p = fmaf(p, f, 0.2402265069f);
    p = fmaf(p, f, 0.6931471806f);
    p = fmaf(p, f, 1.0f);
    return p * __int_as_float(((int)n + 127) << 23);
}

__global__ void __launch_bounds__(256) softmax_k(float* __restrict__ logits) {
    float* p = logits + (size_t)blockIdx.x * Ss;
    const int tid = threadIdx.x;
    float v[8];
#pragma unroll
    for (int i = 0; i < 8; i++) v[i] = p[tid + 256 * i];
    float m = v[0];
#pragma unroll
    for (int i = 1; i < 8; i++) m = fmaxf(m, v[i]);
#pragma unroll
    for (int o = 16; o; o >>= 1) m = fmaxf(m, __shfl_xor_sync(0xffffffffu, m, o));
    __shared__ float rmax[8], rsum[8];
    if ((tid & 31) == 0) rmax[tid >> 5] = m;
    __syncthreads();
#pragma unroll
    for (int i = 0; i < 8; i++) m = fmaxf(m, rmax[i]);
    float s = 0.f;
#pragma unroll
    for (int i = 0; i < 8; i++) { v[i] = fexp(v[i] - m); s += v[i]; }
#pragma unroll
    for (int o = 16; o; o >>= 1) s += __shfl_xor_sync(0xffffffffu, s, o);
    if ((tid & 31) == 0) rsum[tid >> 5] = s;
    __syncthreads();
    s = 0.f;
#pragma unroll
    for (int i = 0; i < 8; i++) s += rsum[i];
    float inv = 1.f / s;
#pragma unroll
    for (int i = 0; i < 8; i++) p[tid + 256 * i] = v[i] * inv;
}

__global__ void __launch_bounds__(256) ln_relu_k(
    float* __restrict__ h, const float* __restrict__ g, const float* __restrict__ b)
{
    float* p = h + (size_t)blockIdx.x * Cc;
    const int tid = threadIdx.x;
    float v[4];
    float s = 0.f, ss = 0.f;
#pragma unroll
    for (int i = 0; i < 4; i++) {
        v[i] = p[tid + 256 * i];
        s += v[i];
        ss += v[i] * v[i];
    }
#pragma unroll
    for (int o = 16; o; o >>= 1) {
        s  += __shfl_xor_sync(0xffffffffu, s, o);
        ss += __shfl_xor_sync(0xffffffffu, ss, o);
    }
    __shared__ float r1[8], r2[8];
    if ((tid & 31) == 0) { r1[tid >> 5] = s; r2[tid >> 5] = ss; }
    __syncthreads();
    s = 0.f; ss = 0.f;
#pragma unroll
    for (int i = 0; i < 8; i++) { s += r1[i]; ss += r2[i]; }
    float mean = s * (1.f / Cc);
    float var  = ss * (1.f / Cc) - mean * mean;
    float inv  = rsqrtf(var + 1e-5f);
#pragma unroll
    for (int i = 0; i < 4; i++) {
        int c = tid + 256 * i;
        float y = (v[i] - mean) * inv * g[c] + b[c];
        p[c] = fmaxf(y, 0.f);
    }
}

// ---------------------------------------------------------------------------
extern "C" void kernel_launch(void* const* d_in, const int* in_sizes, int n_in,
                              void* d_out, int out_size)
{
    (void)in_sizes; (void)n_in; (void)out_size;
    const float* x       = (const float*)d_in[0];
    const float* lfb     = (const float*)d_in[1];
    const float* theta_w = (const float*)d_in[2];
    const float* theta_b = (const float*)d_in[3];
    const float* phi_w   = (const float*)d_in[4];
    const float* phi_b   = (const float*)d_in[5];
    const float* gi_w    = (const float*)d_in[6];
    const float* gi_b    = (const float*)d_in[7];
    const float* ln_g    = (const float*)d_in[8];
    const float* ln_b    = (const float*)d_in[9];
    const float* fc_w    = (const float*)d_in[10];
    const float* fc_b    = (const float*)d_in[11];
    float* out = (float*)d_out;

    float *theta, *phi, *giT, *logits, *att;
    cudaGetSymbolAddress((void**)&theta,  g_theta);
    cudaGetSymbolAddress((void**)&phi,    g_phi);
    cudaGetSymbolAddress((void**)&giT,    g_giT);
    cudaGetSymbolAddress((void**)&logits, g_logits);
    cudaGetSymbolAddress((void**)&att,    g_att);

    cudaFuncSetAttribute(gemm_cp<true,  false>,
        cudaFuncAttributeMaxDynamicSharedMemorySize, SMEM_ALL);
    cudaFuncSetAttribute(gemm_cp<false, false>,
        cudaFuncAttributeMaxDynamicSharedMemorySize, SMEM_ALL);
    cudaFuncSetAttribute(gemm_cp<false, true>,
        cudaFuncAttributeMaxDynamicSharedMemorySize, SMEM_ALL);

    dim3 blk(256);
    const float scale = 32.0f;   // sqrt(C)

    // theta = x @ theta_w^T + theta_b                [8192,1024]  (split)
    gemm_cp<true, false><<<dim3(8, 64, 1), blk, SMEM_ALL>>>(
        x, theta_w, theta_b, nullptr, theta, Cc, Cc, 1.f, 0, 0, 0);
    // phi = lfb @ phi_w^T + phi_b                    [16384,1024] (split)
    gemm_cp<true, false><<<dim3(8, 128, 1), blk, SMEM_ALL>>>(
        lfb, phi_w, phi_b, nullptr, phi, Cc, Cc, 1.f, 0, 0, 0);
    // giT[b][c][s] = (lfb @ gi_w^T + gi_b)^T         (single, transposed out)
    gemm_cp<false, true><<<dim3(8, 128, 1), blk, SMEM_ALL>>>(
        lfb, gi_w, gi_b, nullptr, giT, Cc, Cc, 1.f, 0, 0, 0);
    // logits[b] = 32 * theta[b] @ phi[b]^T           [1024,2048]x8 (split)
    gemm_cp<true, false><<<dim3(16, 8, Bv), blk, SMEM_ALL>>>(
        theta, phi, nullptr, nullptr, logits, Ss, Cc, scale,
        (size_t)Tt * Cc, (size_t)Ss * Cc, (size_t)Tt * Ss);
    softmax_k<<<Bv * Tt, blk>>>(logits);
    // att[b] = attn[b] @ giT[b]^T                    [1024,1024]x8 (single NT)
    gemm_cp<false, false><<<dim3(8, 8, Bv), blk, SMEM_ALL>>>(
        logits, giT, nullptr, nullptr, att, Cc, Ss, 1.f,
        (size_t)Tt * Ss, (size_t)Cc * Ss, (size_t)Tt * Cc);
    ln_relu_k<<<Bv * Tt, blk>>>(att, ln_g, ln_b);
    // out = relu(LN(att)) @ fc_w^T + fc_b + x        [8192,1024]  (single)
    gemm_cp<false, false><<<dim3(8, 64, 1), blk, SMEM_ALL>>>(
        att, fc_w, fc_b, x, out, Cc, Cc, 1.f, 0, 0, 0);
}

// round 11
// speedup vs baseline: 2.8049x; 1.2162x over previous
#include <cuda_runtime.h>
#include <math.h>
#include <stdint.h>

// ---------------------------------------------------------------------------
// _NLBlock on GB300, legacy mma.sync tf32 (compute_103-safe).
// R9: algebraic reduction of the logit chain:
//   logits[t,s] = x_t^T (thw^T phw) lfb_s + const(t) + v.lfb_s + const
// softmax kills per-row constants, so:
//   Mt = phw^T thw  (tiny split GEMM via transposes)
//   P  = x @ Mt^T-contraction (split)       [B*T, C]
//   logits = 32*(P @ lfb^T) + 32*(lfb.v)    (split, bias-with-batch-stride)
// phi GEMM (51.6 G-FMA-units) eliminated. Rest as R8: 2 CTAs/SM, cp.async
// 3-stage, XOR16 smem, split-at-use 3xTF32, transposed gi (all GEMMs NT).
// ---------------------------------------------------------------------------

#define Bv 8
#define Tt 1024
#define Ss 2048
#define Cc 1024

__device__ float g_P     [Bv * Tt * Cc];   // x @ Mt
__device__ float g_giT   [Bv * Cc * Ss];   // gi transposed: [b][c][s]
__device__ float g_logits[Bv * Tt * Ss];
__device__ float g_att   [Bv * Tt * Cc];
__device__ float g_twT   [Cc * Cc];        // theta_w^T
__device__ float g_pwT   [Cc * Cc];        // phi_w^T
__device__ float g_Mt    [Cc * Cc];        // Mt[c',c] = sum_o phw[o,c'] thw[o,c]
__device__ float g_v     [Cc];             // v[c'] = sum_o theta_b[o] phi_w[o,c']
__device__ float g_cb    [Bv * Ss];        // 32 * lfb[b,s,:].v

__device__ __forceinline__ uint32_t fu(float f) { return __float_as_uint(f); }

__device__ __forceinline__ float rtf32(float x) {
    uint32_t u;
    asm("cvt.rna.tf32.f32 %0, %1;" : "=r"(u) : "f"(x));
    return __uint_as_float(u);
}

__device__ __forceinline__ uint32_t s2u(const void* p) {
    uint32_t a;
    asm("{ .reg .u64 t; cvta.to.shared.u64 t, %1; cvt.u32.u64 %0, t; }"
        : "=r"(a) : "l"(p));
    return a;
}

__device__ __forceinline__ float lds32(uint32_t a) {
    float v;
    asm volatile("ld.shared.f32 %0, [%1];" : "=f"(v) : "r"(a));
    return v;
}

__device__ __forceinline__ void cpa16(uint32_t s, const void* g) {
    asm volatile("cp.async.cg.shared.global [%0], [%1], 16;"
                 :: "r"(s), "l"(g) : "memory");
}
#define CP_COMMIT() asm volatile("cp.async.commit_group;" ::: "memory")
#define CP_WAIT(n)  asm volatile("cp.async.wait_group %0;" :: "n"(n) : "memory")

__device__ __forceinline__ void mma8(float* d, uint32_t a0, uint32_t a1,
                                     uint32_t a2, uint32_t a3,
                                     uint32_t b0, uint32_t b1) {
    asm("mma.sync.aligned.m16n8k8.row.col.f32.tf32.tf32.f32 "
        "{%0,%1,%2,%3}, {%4,%5,%6,%7}, {%8,%9}, {%0,%1,%2,%3};"
        : "+f"(d[0]), "+f"(d[1]), "+f"(d[2]), "+f"(d[3])
        : "r"(a0), "r"(a1), "r"(a2), "r"(a3), "r"(b0), "r"(b1));
}

// smem tile: 128 rows x 128B (32 fp32, k natural order), 16B-block XOR swizzle
constexpr int STAGE = 32768;                    // A 16KB + B 16KB
constexpr int NSTG  = 3;
constexpr int SMEM_ALL = 1024 + NSTG * STAGE;   // 99328; x2 CTAs = 194KB/SM

// ---------------------------------------------------------------------------
// NT GEMM, CTA tile 128x128x32, 256 thr (8 warps: 2M x 4N, 64x32 per warp)
//   SPLIT: hi/lo 3xTF32 at fragment use   TRANS: write C transposed [n][m]
//   C = alpha * A@B^T (+bias[z*sBias + n]) (+res)
// ---------------------------------------------------------------------------
template <bool SPLIT, bool TRANS>
__global__ void __launch_bounds__(256, 2) gemm_cp(
    const float* __restrict__ A, const float* __restrict__ B,
    const float* __restrict__ bias, const float* __restrict__ res,
    float* __restrict__ C,
    int N, int K, float alpha,
    size_t sA, size_t sB, size_t sC, size_t sBias)
{
    extern __shared__ char sm[];
    const uint32_t sb = s2u(sm);
    const int tid  = threadIdx.x;
    const int lane = tid & 31;
    const int wid  = tid >> 5;
    const int wm   = wid >> 2;
    const int wn   = wid & 3;
    const int n0   = blockIdx.x * 128;

    const float* Ag = A + blockIdx.z * sA + (size_t)blockIdx.y * 128 * K;
    const float* Bg = B + blockIdx.z * sB + (size_t)n0 * K;
    float* Cg = C + blockIdx.z * sC;
    const float* Rg = res ? res + blockIdx.z * sC : nullptr;

    float* sbias = (float*)sm;                  // 512 B
    if (bias && tid < 128) sbias[tid] = bias[blockIdx.z * sBias + n0 + tid];

    // per-thread cp.async tasks: 1024 16B-copies per tile, 4 per thread
    size_t   goff[4];
    uint32_t soff[4];
#pragma unroll
    for (int i = 0; i < 4; i++) {
        int v = i * 256 + tid;
        int r = v >> 3, c4 = v & 7;
        goff[i] = (size_t)r * K + c4 * 4;
        soff[i] = (uint32_t)(r * 128 + ((c4 * 16) ^ ((r & 7) << 4)));
    }
    const uint32_t stg0 = sb + 1024;

#define ISSUE(CK)                                                             \
    {                                                                         \
        uint32_t st = stg0 + ((CK) % NSTG) * STAGE;                           \
        int k0 = (CK) * 32;                                                   \
        _Pragma("unroll")                                                     \
        for (int i = 0; i < 4; i++)                                           \
            cpa16(st + soff[i], Ag + goff[i] + k0);                           \
        _Pragma("unroll")                                                     \
        for (int i = 0; i < 4; i++)                                           \
            cpa16(st + 16384 + soff[i], Bg + goff[i] + k0);                   \
        CP_COMMIT();                                                          \
    }

    float acc[4][4][4];
#pragma unroll
    for (int mt = 0; mt < 4; mt++)
#pragma unroll
        for (int nt = 0; nt < 4; nt++)
#pragma unroll
            for (int e = 0; e < 4; e++) acc[mt][nt][e] = 0.f;

    const int NC = K / 32;
    ISSUE(0);
    ISSUE(1);

    const uint32_t cB = (uint32_t)(lane & 3) * 4;   // k-lane byte offset
    const int      rq = lane >> 2;

    for (int ck = 0; ck < NC; ck++) {
        if (ck + 1 < NC) { CP_WAIT(1); } else { CP_WAIT(0); }
        __syncthreads();
        if (ck + 2 < NC) ISSUE(ck + 2);

        const uint32_t AS = stg0 + (ck % NSTG) * STAGE;
        const uint32_t BS = AS + 16384;

        // j-outer: hold only one k-step of fragments (regs <= 128 for occ 2)
#pragma unroll
        for (int j = 0; j < 4; j++) {
            const uint32_t jb = (uint32_t)(j * 32) + cB;

            float bh[4][2], bl[4][2];
#pragma unroll
            for (int nt = 0; nt < 4; nt++) {
                int row = wn * 32 + nt * 8 + rq;
                uint32_t rb = BS + row * 128;
                uint32_t sw = (uint32_t)((row & 7) << 4);
#pragma unroll
                for (int p = 0; p < 2; p++) {
                    float x = lds32(rb + ((jb + (uint32_t)(p * 16)) ^ sw));
                    if (SPLIT) {
                        float h = __uint_as_float(fu(x) & 0xFFFFE000u);
                        bh[nt][p] = h; bl[nt][p] = x - h;
                    } else {
                        bh[nt][p] = rtf32(x);
                    }
                }
            }
#pragma unroll
            for (int mt = 0; mt < 4; mt++) {
                float ah[2][2], al[2][2];
#pragma unroll
                for (int rr = 0; rr < 2; rr++) {
                    int row = wm * 64 + mt * 16 + rq + rr * 8;
                    uint32_t rb = AS + row * 128;
                    uint32_t sw = (uint32_t)((row & 7) << 4);
#pragma unroll
                    for (int p = 0; p < 2; p++) {
                        float x = lds32(rb + ((jb + (uint32_t)(p * 16)) ^ sw));
                        if (SPLIT) {
                            float h = __uint_as_float(fu(x) & 0xFFFFE000u);
                            ah[rr][p] = h; al[rr][p] = x - h;
                        } else {
                            ah[rr][p] = rtf32(x);
                        }
                    }
                }
                uint32_t aH0 = fu(ah[0][0]), aH1 = fu(ah[1][0]);
                uint32_t aH2 = fu(ah[0][1]), aH3 = fu(ah[1][1]);
                uint32_t aL0 = 0, aL1 = 0, aL2 = 0, aL3 = 0;
                if (SPLIT) {
                    aL0 = fu(al[0][0]); aL1 = fu(al[1][0]);
                    aL2 = fu(al[0][1]); aL3 = fu(al[1][1]);
                }
#pragma unroll
                for (int nt = 0; nt < 4; nt++) {
                    uint32_t bH0 = fu(bh[nt][0]), bH1 = fu(bh[nt][1]);
                    mma8(acc[mt][nt], aH0, aH1, aH2, aH3, bH0, bH1);
                    if (SPLIT) {
                        uint32_t bL0 = fu(bl[nt][0]);
                        uint32_t bL1 = fu(bl[nt][1]);
                        mma8(acc[mt][nt], aL0, aL1, aL2, aL3, bH0, bH1);
                        mma8(acc[mt][nt], aH0, aH1, aH2, aH3, bL0, bL1);
                    }
                }
            }
        }
    }

    if (!TRANS) {
#pragma unroll
        for (int mt = 0; mt < 4; mt++) {
            size_t m0 = (size_t)blockIdx.y * 128 + wm * 64 + mt * 16 + rq;
#pragma unroll
            for (int nt = 0; nt < 4; nt++) {
                int cl = wn * 32 + nt * 8 + (lane & 3) * 2;
                int col = n0 + cl;
                float v0 = acc[mt][nt][0] * alpha, v1 = acc[mt][nt][1] * alpha;
                float v2 = acc[mt][nt][2] * alpha, v3 = acc[mt][nt][3] * alpha;
                if (bias) {
                    float b0 = sbias[cl], b1 = sbias[cl + 1];
                    v0 += b0; v1 += b1; v2 += b0; v3 += b1;
                }
                size_t i0 = m0 * N + col, i1 = (m0 + 8) * N + col;
                if (Rg) {
                    v0 += Rg[i0]; v1 += Rg[i0 + 1];
                    v2 += Rg[i1]; v3 += Rg[i1 + 1];
                }
                float2 w0; w0.x = v0; w0.y = v1;
                float2 w1; w1.x = v2; w1.y = v3;
                *(float2*)(Cg + i0) = w0;
                *(float2*)(Cg + i1) = w1;
            }
        }
    } else {
        // transposed epilogue via smem (128 cols x 132-padded rows)
        __syncthreads();                       // stages dead, reuse as buffer
        float* tb = (float*)(sm + 1024);
#pragma unroll
        for (int mt = 0; mt < 4; mt++) {
            int ml = wm * 64 + mt * 16 + rq;
#pragma unroll
            for (int nt = 0; nt < 4; nt++) {
                int cl = wn * 32 + nt * 8 + (lane & 3) * 2;
                float v0 = acc[mt][nt][0] * alpha, v1 = acc[mt][nt][1] * alpha;
                float v2 = acc[mt][nt][2] * alpha, v3 = acc[mt][nt][3] * alpha;
                if (bias) {
                    float b0 = sbias[cl], b1 = sbias[cl + 1];
                    v0 += b0; v1 += b1; v2 += b0; v3 += b1;
                }
                tb[cl * 132 + ml]           = v0;
                tb[(cl + 1) * 132 + ml]     = v1;
                tb[cl * 132 + ml + 8]       = v2;
                tb[(cl + 1) * 132 + ml + 8] = v3;
            }
        }
        __syncthreads();
        size_t mg_base = (size_t)blockIdx.y * 128 + lane * 4;
        size_t b  = mg_base >> 11;             // 2048 rows per batch
        size_t s  = mg_base & 2047;
        float* Ct = C + b * (size_t)Cc * Ss + s;
#pragma unroll
        for (int rr = 0; rr < 16; rr++) {
            int n = wid * 16 + rr;
            float4 v = *(const float4*)(tb + n * 132 + lane * 4);
            *(float4*)(Ct + (size_t)(n0 + n) * Ss) = v;
        }
    }
#undef ISSUE
}

// ---------------------------------------------------------------------------
// 1024x1024 fp32 transpose (32x32 tiles)
// ---------------------------------------------------------------------------
__global__ void __launch_bounds__(256) transpose_k(
    const float* __restrict__ in, float* __restrict__ out)
{
    __shared__ float t[32][33];
    int x = blockIdx.x * 32 + threadIdx.x;
    int y = blockIdx.y * 32 + threadIdx.y;
#pragma unroll
    for (int i = 0; i < 32; i += 8)
        t[threadIdx.y + i][threadIdx.x] = in[(size_t)(y + i) * Cc + x];
    __syncthreads();
    x = blockIdx.y * 32 + threadIdx.x;
    y = blockIdx.x * 32 + threadIdx.y;
#pragma unroll
    for (int i = 0; i < 32; i += 8)
        out[(size_t)(y + i) * Cc + x] = t[threadIdx.x][threadIdx.y + i];
}

// v[c'] = sum_o theta_b[o] * phi_w[o,c']
__global__ void __launch_bounds__(256) vker(
    const float* __restrict__ tb, const float* __restrict__ pw,
    float* __restrict__ v)
{
    int c = blockIdx.x * 256 + threadIdx.x;
    float s = 0.f;
    for (int o = 0; o < Cc; o++) s = fmaf(tb[o], pw[(size_t)o * Cc + c], s);
    v[c] = s;
}

// cb[b*S+s] = 32 * dot(lfb[b,s,:], v)
__global__ void __launch_bounds__(256) cbias_k(
    const float* __restrict__ lfb, const float* __restrict__ v,
    float* __restrict__ cb)
{
    const float* p = lfb + (size_t)blockIdx.x * Cc;
    const int tid = threadIdx.x;
    float s = 0.f;
#pragma unroll
    for (int i = 0; i < 4; i++) {
        int c = tid + 256 * i;
        s = fmaf(p[c], v[c], s);
    }
#pragma unroll
    for (int o = 16; o; o >>= 1) s += __shfl_xor_sync(0xffffffffu, s, o);
    __shared__ float r1[8];
    if ((tid & 31) == 0) r1[tid >> 5] = s;
    __syncthreads();
    if (tid == 0) {
        float t = 0.f;
#pragma unroll
        for (int i = 0; i < 8; i++) t += r1[i];
        cb[blockIdx.x] = 32.0f * t;
    }
}

// ---------------------------------------------------------------------------
__device__ __forceinline__ float fexp(float x) {
    float t = fmaxf(x * 1.4426950408889634f, -126.f);
    float n = rintf(t);
    float f = t - n;
    float p = 0.0013333558f;
    p = fmaf(p, f, 0.0096181291f);
    p = fmaf(p, f, 0.0555041087f);
    p = fmaf(p, f, 0.2402265069f);
    p = fmaf(p, f, 0.6931471806f);
    p = fmaf(p, f, 1.0f);
    return p * __int_as_float(((int)n + 127) << 23);
}

__global__ void __launch_bounds__(256) softmax_k(float* __restrict__ logits) {
    float* p = logits + (size_t)blockIdx.x * Ss;
    const int tid = threadIdx.x;
    float v[8];
#pragma unroll
    for (int i = 0; i < 8; i++) v[i] = p[tid + 256 * i];
    float m = v[0];
#pragma unroll
    for (int i = 1; i < 8; i++) m = fmaxf(m, v[i]);
#pragma unroll
    for (int o = 16; o; o >>= 1) m = fmaxf(m, __shfl_xor_sync(0xffffffffu, m, o));
    __shared__ float rmax[8], rsum[8];
    if ((tid & 31) == 0) rmax[tid >> 5] = m;
    __syncthreads();
#pragma unroll
    for (int i = 0; i < 8; i++) m = fmaxf(m, rmax[i]);
    float s = 0.f;
#pragma unroll
    for (int i = 0; i < 8; i++) { v[i] = fexp(v[i] - m); s += v[i]; }
#pragma unroll
    for (int o = 16; o; o >>= 1) s += __shfl_xor_sync(0xffffffffu, s, o);
    if ((tid & 31) == 0) rsum[tid >> 5] = s;
    __syncthreads();
    s = 0.f;
#pragma unroll
    for (int i = 0; i < 8; i++) s += rsum[i];
    float inv = 1.f / s;
#pragma unroll
    for (int i = 0; i < 8; i++) p[tid + 256 * i] = v[i] * inv;
}

__global__ void __launch_bounds__(256) ln_relu_k(
    float* __restrict__ h, const float* __restrict__ g, const float* __restrict__ b)
{
    float* p = h + (size_t)blockIdx.x * Cc;
    const int tid = threadIdx.x;
    float v[4];
    float s = 0.f, ss = 0.f;
#pragma unroll
    for (int i = 0; i < 4; i++) {
        v[i] = p[tid + 256 * i];
        s += v[i];
        ss += v[i] * v[i];
    }
#pragma unroll
    for (int o = 16; o; o >>= 1) {
        s  += __shfl_xor_sync(0xffffffffu, s, o);
        ss += __shfl_xor_sync(0xffffffffu, ss, o);
    }
    __shared__ float r1[8], r2[8];
    if ((tid & 31) == 0) { r1[tid >> 5] = s; r2[tid >> 5] = ss; }
    __syncthreads();
    s = 0.f; ss = 0.f;
#pragma unroll
    for (int i = 0; i < 8; i++) { s += r1[i]; ss += r2[i]; }
    float mean = s * (1.f / Cc);
    float var  = ss * (1.f / Cc) - mean * mean;
    float inv  = rsqrtf(var + 1e-5f);
#pragma unroll
    for (int i = 0; i < 4; i++) {
        int c = tid + 256 * i;
        float y = (v[i] - mean) * inv * g[c] + b[c];
        p[c] = fmaxf(y, 0.f);
    }
}

// ---------------------------------------------------------------------------
extern "C" void kernel_launch(void* const* d_in, const int* in_sizes, int n_in,
                              void* d_out, int out_size)
{
    (void)in_sizes; (void)n_in; (void)out_size;
    const float* x       = (const float*)d_in[0];
    const float* lfb     = (const float*)d_in[1];
    const float* theta_w = (const float*)d_in[2];
    const float* theta_b = (const float*)d_in[3];
    const float* phi_w   = (const float*)d_in[4];
    const float* phi_b   = (const float*)d_in[5];
    const float* gi_w    = (const float*)d_in[6];
    const float* gi_b    = (const float*)d_in[7];
    const float* ln_g    = (const float*)d_in[8];
    const float* ln_b    = (const float*)d_in[9];
    const float* fc_w    = (const float*)d_in[10];
    const float* fc_b    = (const float*)d_in[11];
    float* out = (float*)d_out;

    float *P, *giT, *logits, *att, *twT, *pwT, *Mt, *v, *cb;
    cudaGetSymbolAddress((void**)&P,      g_P);
    cudaGetSymbolAddress((void**)&giT,    g_giT);
    cudaGetSymbolAddress((void**)&logits, g_logits);
    cudaGetSymbolAddress((void**)&att,    g_att);
    cudaGetSymbolAddress((void**)&twT,    g_twT);
    cudaGetSymbolAddress((void**)&pwT,    g_pwT);
    cudaGetSymbolAddress((void**)&Mt,     g_Mt);
    cudaGetSymbolAddress((void**)&v,      g_v);
    cudaGetSymbolAddress((void**)&cb,     g_cb);

    cudaFuncSetAttribute(gemm_cp<true,  false>,
        cudaFuncAttributeMaxDynamicSharedMemorySize, SMEM_ALL);
    cudaFuncSetAttribute(gemm_cp<false, false>,
        cudaFuncAttributeMaxDynamicSharedMemorySize, SMEM_ALL);
    cudaFuncSetAttribute(gemm_cp<false, true>,
        cudaFuncAttributeMaxDynamicSharedMemorySize, SMEM_ALL);

    dim3 blk(256);

    // --- logit-chain precomputation (phi projection eliminated) ---
    transpose_k<<<dim3(32, 32), dim3(32, 8)>>>(theta_w, twT);
    transpose_k<<<dim3(32, 32), dim3(32, 8)>>>(phi_w, pwT);
    // Mt[c',c] = sum_o phw[o,c'] thw[o,c]   (split, tiny)
    gemm_cp<true, false><<<dim3(8, 8, 1), blk, SMEM_ALL>>>(
        pwT, twT, nullptr, nullptr, Mt, Cc, Cc, 1.f, 0, 0, 0, 0);
    vker<<<4, blk>>>(theta_b, phi_w, v);
    cbias_k<<<Bv * Ss, blk>>>(lfb, v, cb);
    // P[t,c'] = sum_c x[t,c] Mt[c',c]               [8192,1024]  (split)
    gemm_cp<true, false><<<dim3(8, 64, 1), blk, SMEM_ALL>>>(
        x, Mt, nullptr, nullptr, P, Cc, Cc, 1.f, 0, 0, 0, 0);
    // giT[b][c][s] = (lfb @ gi_w^T + gi_b)^T        (single, transposed out)
    gemm_cp<false, true><<<dim3(8, 128, 1), blk, SMEM_ALL>>>(
        lfb, gi_w, gi_b, nullptr, giT, Cc, Cc, 1.f, 0, 0, 0, 0);
    // logits[b] = 32 * P[b] @ lfb[b]^T + cb[b,s]    [1024,2048]x8 (split)
    gemm_cp<true, false><<<dim3(16, 8, Bv), blk, SMEM_ALL>>>(
        P, lfb, cb, nullptr, logits, Ss, Cc, 32.f,
        (size_t)Tt * Cc, (size_t)Ss * Cc, (size_t)Tt * Ss, (size_t)Ss);
    softmax_k<<<Bv * Tt, blk>>>(logits);
    // att[b] = attn[b] @ giT[b]^T                   [1024,1024]x8 (single NT)
    gemm_cp<false, false><<<dim3(8, 8, Bv), blk, SMEM_ALL>>>(
        logits, giT, nullptr, nullptr, att, Cc, Ss, 1.f,
        (size_t)Tt * Ss, (size_t)Cc * Ss, (size_t)Tt * Cc, 0);
    ln_relu_k<<<Bv * Tt, blk>>>(att, ln_g, ln_b);
    // out = relu(LN(att)) @ fc_w^T + fc_b + x       [8192,1024]  (single)
    gemm_cp<false, false><<<dim3(8, 64, 1), blk, SMEM_ALL>>>(
        att, fc_w, fc_b, x, out, Cc, Cc, 1.f, 0, 0, 0, 0);
}

// round 12
// speedup vs baseline: 2.9527x; 1.0527x over previous
#include <cuda_runtime.h>
#include <math.h>
#include <stdint.h>

// ---------------------------------------------------------------------------
// _NLBlock on GB300, legacy mma.sync tf32 (compute_103-safe).
// R10 = R9 (bilinear logit reduction, 2 CTAs/SM, cp.async 3-stage, XOR16,
// split-at-use 3xTF32, transposed gi) +
//   - vker parallelized (deterministic two-phase split-o)
//   - cbias warp-per-row
//   - softmax float4 I/O
//   - stream-forked overlap: giT and the v/cb chain run concurrently with
//     the transpose->Mt->P->logits critical path (graph-capture-safe
//     event fork/join on non-blocking streams).
// ---------------------------------------------------------------------------

#define Bv 8
#define Tt 1024
#define Ss 2048
#define Cc 1024

__device__ float g_P     [Bv * Tt * Cc];   // x @ Mt
__device__ float g_giT   [Bv * Cc * Ss];   // gi transposed: [b][c][s]
__device__ float g_logits[Bv * Tt * Ss];
__device__ float g_att   [Bv * Tt * Cc];
__device__ float g_twT   [Cc * Cc];        // theta_w^T
__device__ float g_pwT   [Cc * Cc];        // phi_w^T
__device__ float g_Mt    [Cc * Cc];        // Mt[c',c] = sum_o phw[o,c'] thw[o,c]
__device__ float g_vp    [32 * Cc];        // vker partials
__device__ float g_v     [Cc];             // v[c'] = sum_o theta_b[o] phi_w[o,c']
__device__ float g_cb    [Bv * Ss];        // 32 * lfb[b,s,:].v

__device__ __forceinline__ uint32_t fu(float f) { return __float_as_uint(f); }

__device__ __forceinline__ float rtf32(float x) {
    uint32_t u;
    asm("cvt.rna.tf32.f32 %0, %1;" : "=r"(u) : "f"(x));
    return __uint_as_float(u);
}

__device__ __forceinline__ uint32_t s2u(const void* p) {
    uint32_t a;
    asm("{ .reg .u64 t; cvta.to.shared.u64 t, %1; cvt.u32.u64 %0, t; }"
        : "=r"(a) : "l"(p));
    return a;
}

__device__ __forceinline__ float lds32(uint32_t a) {
    float v;
    asm volatile("ld.shared.f32 %0, [%1];" : "=f"(v) : "r"(a));
    return v;
}

__device__ __forceinline__ void cpa16(uint32_t s, const void* g) {
    asm volatile("cp.async.cg.shared.global [%0], [%1], 16;"
                 :: "r"(s), "l"(g) : "memory");
}
#define CP_COMMIT() asm volatile("cp.async.commit_group;" ::: "memory")
#define CP_WAIT(n)  asm volatile("cp.async.wait_group %0;" :: "n"(n) : "memory")

__device__ __forceinline__ void mma8(float* d, uint32_t a0, uint32_t a1,
                                     uint32_t a2, uint32_t a3,
                                     uint32_t b0, uint32_t b1) {
    asm("mma.sync.aligned.m16n8k8.row.col.f32.tf32.tf32.f32 "
        "{%0,%1,%2,%3}, {%4,%5,%6,%7}, {%8,%9}, {%0,%1,%2,%3};"
        : "+f"(d[0]), "+f"(d[1]), "+f"(d[2]), "+f"(d[3])
        : "r"(a0), "r"(a1), "r"(a2), "r"(a3), "r"(b0), "r"(b1));
}

constexpr int STAGE = 32768;                    // A 16KB + B 16KB
constexpr int NSTG  = 3;
constexpr int SMEM_ALL = 1024 + NSTG * STAGE;   // 99328; x2 CTAs = 194KB/SM

// ---------------------------------------------------------------------------
// NT GEMM, CTA tile 128x128x32, 256 thr (8 warps: 2M x 4N, 64x32 per warp)
//   SPLIT: hi/lo 3xTF32 at fragment use   TRANS: write C transposed [n][m]
//   C = alpha * A@B^T (+bias[z*sBias + n]) (+res)
// ---------------------------------------------------------------------------
template <bool SPLIT, bool TRANS>
__global__ void __launch_bounds__(256, 2) gemm_cp(
    const float* __restrict__ A, const float* __restrict__ B,
    const float* __restrict__ bias, const float* __restrict__ res,
    float* __restrict__ C,
    int N, int K, float alpha,
    size_t sA, size_t sB, size_t sC, size_t sBias)
{
    extern __shared__ char sm[];
    const uint32_t sb = s2u(sm);
    const int tid  = threadIdx.x;
    const int lane = tid & 31;
    const int wid  = tid >> 5;
    const int wm   = wid >> 2;
    const int wn   = wid & 3;
    const int n0   = blockIdx.x * 128;

    const float* Ag = A + blockIdx.z * sA + (size_t)blockIdx.y * 128 * K;
    const float* Bg = B + blockIdx.z * sB + (size_t)n0 * K;
    float* Cg = C + blockIdx.z * sC;
    const float* Rg = res ? res + blockIdx.z * sC : nullptr;

    float* sbias = (float*)sm;                  // 512 B
    if (bias && tid < 128) sbias[tid] = bias[blockIdx.z * sBias + n0 + tid];

    size_t   goff[4];
    uint32_t soff[4];
#pragma unroll
    for (int i = 0; i < 4; i++) {
        int v = i * 256 + tid;
        int r = v >> 3, c4 = v & 7;
        goff[i] = (size_t)r * K + c4 * 4;
        soff[i] = (uint32_t)(r * 128 + ((c4 * 16) ^ ((r & 7) << 4)));
    }
    const uint32_t stg0 = sb + 1024;

#define ISSUE(CK)                                                             \
    {                                                                         \
        uint32_t st = stg0 + ((CK) % NSTG) * STAGE;                           \
        int k0 = (CK) * 32;                                                   \
        _Pragma("unroll")                                                     \
        for (int i = 0; i < 4; i++)                                           \
            cpa16(st + soff[i], Ag + goff[i] + k0);                           \
        _Pragma("unroll")                                                     \
        for (int i = 0; i < 4; i++)                                           \
            cpa16(st + 16384 + soff[i], Bg + goff[i] + k0);                   \
        CP_COMMIT();                                                          \
    }

    float acc[4][4][4];
#pragma unroll
    for (int mt = 0; mt < 4; mt++)
#pragma unroll
        for (int nt = 0; nt < 4; nt++)
#pragma unroll
            for (int e = 0; e < 4; e++) acc[mt][nt][e] = 0.f;

    const int NC = K / 32;
    ISSUE(0);
    ISSUE(1);

    const uint32_t cB = (uint32_t)(lane & 3) * 4;
    const int      rq = lane >> 2;

    for (int ck = 0; ck < NC; ck++) {
        if (ck + 1 < NC) { CP_WAIT(1); } else { CP_WAIT(0); }
        __syncthreads();
        if (ck + 2 < NC) ISSUE(ck + 2);

        const uint32_t AS = stg0 + (ck % NSTG) * STAGE;
        const uint32_t BS = AS + 16384;

#pragma unroll
        for (int j = 0; j < 4; j++) {
            const uint32_t jb = (uint32_t)(j * 32) + cB;

            float bh[4][2], bl[4][2];
#pragma unroll
            for (int nt = 0; nt < 4; nt++) {
                int row = wn * 32 + nt * 8 + rq;
                uint32_t rb = BS + row * 128;
                uint32_t sw = (uint32_t)((row & 7) << 4);
#pragma unroll
                for (int p = 0; p < 2; p++) {
                    float x = lds32(rb + ((jb + (uint32_t)(p * 16)) ^ sw));
                    if (SPLIT) {
                        float h = __uint_as_float(fu(x) & 0xFFFFE000u);
                        bh[nt][p] = h; bl[nt][p] = x - h;
                    } else {
                        bh[nt][p] = rtf32(x);
                    }
                }
            }
#pragma unroll
            for (int mt = 0; mt < 4; mt++) {
                float ah[2][2], al[2][2];
#pragma unroll
                for (int rr = 0; rr < 2; rr++) {
                    int row = wm * 64 + mt * 16 + rq + rr * 8;
                    uint32_t rb = AS + row * 128;
                    uint32_t sw = (uint32_t)((row & 7) << 4);
#pragma unroll
                    for (int p = 0; p < 2; p++) {
                        float x = lds32(rb + ((jb + (uint32_t)(p * 16)) ^ sw));
                        if (SPLIT) {
                            float h = __uint_as_float(fu(x) & 0xFFFFE000u);
                            ah[rr][p] = h; al[rr][p] = x - h;
                        } else {
                            ah[rr][p] = rtf32(x);
                        }
                    }
                }
                uint32_t aH0 = fu(ah[0][0]), aH1 = fu(ah[1][0]);
                uint32_t aH2 = fu(ah[0][1]), aH3 = fu(ah[1][1]);
                uint32_t aL0 = 0, aL1 = 0, aL2 = 0, aL3 = 0;
                if (SPLIT) {
                    aL0 = fu(al[0][0]); aL1 = fu(al[1][0]);
                    aL2 = fu(al[0][1]); aL3 = fu(al[1][1]);
                }
#pragma unroll
                for (int nt = 0; nt < 4; nt++) {
                    uint32_t bH0 = fu(bh[nt][0]), bH1 = fu(bh[nt][1]);
                    mma8(acc[mt][nt], aH0, aH1, aH2, aH3, bH0, bH1);
                    if (SPLIT) {
                        uint32_t bL0 = fu(bl[nt][0]);
                        uint32_t bL1 = fu(bl[nt][1]);
                        mma8(acc[mt][nt], aL0, aL1, aL2, aL3, bH0, bH1);
                        mma8(acc[mt][nt], aH0, aH1, aH2, aH3, bL0, bL1);
                    }
                }
            }
        }
    }

    if (!TRANS) {
#pragma unroll
        for (int mt = 0; mt < 4; mt++) {
            size_t m0 = (size_t)blockIdx.y * 128 + wm * 64 + mt * 16 + rq;
#pragma unroll
            for (int nt = 0; nt < 4; nt++) {
                int cl = wn * 32 + nt * 8 + (lane & 3) * 2;
                int col = n0 + cl;
                float v0 = acc[mt][nt][0] * alpha, v1 = acc[mt][nt][1] * alpha;
                float v2 = acc[mt][nt][2] * alpha, v3 = acc[mt][nt][3] * alpha;
                if (bias) {
                    float b0 = sbias[cl], b1 = sbias[cl + 1];
                    v0 += b0; v1 += b1; v2 += b0; v3 += b1;
                }
                size_t i0 = m0 * N + col, i1 = (m0 + 8) * N + col;
                if (Rg) {
                    v0 += Rg[i0]; v1 += Rg[i0 + 1];
                    v2 += Rg[i1]; v3 += Rg[i1 + 1];
                }
                float2 w0; w0.x = v0; w0.y = v1;
                float2 w1; w1.x = v2; w1.y = v3;
                *(float2*)(Cg + i0) = w0;
                *(float2*)(Cg + i1) = w1;
            }
        }
    } else {
        __syncthreads();                       // stages dead, reuse as buffer
        float* tb = (float*)(sm + 1024);
#pragma unroll
        for (int mt = 0; mt < 4; mt++) {
            int ml = wm * 64 + mt * 16 + rq;
#pragma unroll
            for (int nt = 0; nt < 4; nt++) {
                int cl = wn * 32 + nt * 8 + (lane & 3) * 2;
                float v0 = acc[mt][nt][0] * alpha, v1 = acc[mt][nt][1] * alpha;
                float v2 = acc[mt][nt][2] * alpha, v3 = acc[mt][nt][3] * alpha;
                if (bias) {
                    float b0 = sbias[cl], b1 = sbias[cl + 1];
                    v0 += b0; v1 += b1; v2 += b0; v3 += b1;
                }
                tb[cl * 132 + ml]           = v0;
                tb[(cl + 1) * 132 + ml]     = v1;
                tb[cl * 132 + ml + 8]       = v2;
                tb[(cl + 1) * 132 + ml + 8] = v3;
            }
        }
        __syncthreads();
        size_t mg_base = (size_t)blockIdx.y * 128 + lane * 4;
        size_t b  = mg_base >> 11;
        size_t s  = mg_base & 2047;
        float* Ct = C + b * (size_t)Cc * Ss + s;
#pragma unroll
        for (int rr = 0; rr < 16; rr++) {
            int n = wid * 16 + rr;
            float4 v = *(const float4*)(tb + n * 132 + lane * 4);
            *(float4*)(Ct + (size_t)(n0 + n) * Ss) = v;
        }
    }
#undef ISSUE
}

// ---------------------------------------------------------------------------
// 1024x1024 fp32 transpose (32x32 tiles)
// ---------------------------------------------------------------------------
__global__ void __launch_bounds__(256) transpose_k(
    const float* __restrict__ in, float* __restrict__ out)
{
    __shared__ float t[32][33];
    int x = blockIdx.x * 32 + threadIdx.x;
    int y = blockIdx.y * 32 + threadIdx.y;
#pragma unroll
    for (int i = 0; i < 32; i += 8)
        t[threadIdx.y + i][threadIdx.x] = in[(size_t)(y + i) * Cc + x];
    __syncthreads();
    x = blockIdx.y * 32 + threadIdx.x;
    y = blockIdx.x * 32 + threadIdx.y;
#pragma unroll
    for (int i = 0; i < 32; i += 8)
        out[(size_t)(y + i) * Cc + x] = t[threadIdx.x][threadIdx.y + i];
}

// vker phase 1: vp[oc][c] = sum_{o in chunk oc} tb[o]*pw[o*C+c]
__global__ void __launch_bounds__(256) vker_part(
    const float* __restrict__ tb, const float* __restrict__ pw,
    float* __restrict__ vp)
{
    int c = blockIdx.x * 256 + threadIdx.x;
    int o0 = blockIdx.y * 32;
    float s = 0.f;
#pragma unroll
    for (int i = 0; i < 32; i++)
        s = fmaf(tb[o0 + i], pw[(size_t)(o0 + i) * Cc + c], s);
    vp[(size_t)blockIdx.y * Cc + c] = s;
}
// vker phase 2: v[c] = sum_oc vp[oc][c]
__global__ void __launch_bounds__(256) vker_red(
    const float* __restrict__ vp, float* __restrict__ v)
{
    int c = blockIdx.x * 256 + threadIdx.x;
    float s = 0.f;
#pragma unroll
    for (int i = 0; i < 32; i++) s += vp[(size_t)i * Cc + c];
    v[c] = s;
}

// cb[row] = 32 * dot(lfb[row,:], v) ; warp per row, 8 rows per block
__global__ void __launch_bounds__(256) cbias_k(
    const float* __restrict__ lfb, const float* __restrict__ v,
    float* __restrict__ cb)
{
    const int lane = threadIdx.x & 31;
    const int w    = threadIdx.x >> 5;
    const size_t row = (size_t)blockIdx.x * 8 + w;
    const float* p = lfb + row * Cc;
    float s = 0.f;
#pragma unroll
    for (int i = 0; i < 32; i++) {
        int c = i * 32 + lane;
        s = fmaf(p[c], v[c], s);
    }
#pragma unroll
    for (int o = 16; o; o >>= 1) s += __shfl_xor_sync(0xffffffffu, s, o);
    if (lane == 0) cb[row] = 32.0f * s;
}

// ---------------------------------------------------------------------------
__device__ __forceinline__ float fexp(float x) {
    float t = fmaxf(x * 1.4426950408889634f, -126.f);
    float n = rintf(t);
    float f = t - n;
    float p = 0.0013333558f;
    p = fmaf(p, f, 0.0096181291f);
    p = fmaf(p, f, 0.0555041087f);
    p = fmaf(p, f, 0.2402265069f);
    p = fmaf(p, f, 0.6931471806f);
    p = fmaf(p, f, 1.0f);
    return p * __int_as_float(((int)n + 127) << 23);
}

__global__ void __launch_bounds__(256) softmax_k(float* __restrict__ logits) {
    float4* p = (float4*)(logits + (size_t)blockIdx.x * Ss);
    const int tid = threadIdx.x;
    float4 va = p[tid], vb = p[tid + 256];
    float v[8] = {va.x, va.y, va.z, va.w, vb.x, vb.y, vb.z, vb.w};
    float m = v[0];
#pragma unroll
    for (int i = 1; i < 8; i++) m = fmaxf(m, v[i]);
#pragma unroll
    for (int o = 16; o; o >>= 1) m = fmaxf(m, __shfl_xor_sync(0xffffffffu, m, o));
    __shared__ float rmax[8], rsum[8];
    if ((tid & 31) == 0) rmax[tid >> 5] = m;
    __syncthreads();
#pragma unroll
    for (int i = 0; i < 8; i++) m = fmaxf(m, rmax[i]);
    float s = 0.f;
#pragma unroll
    for (int i = 0; i < 8; i++) { v[i] = fexp(v[i] - m); s += v[i]; }
#pragma unroll
    for (int o = 16; o; o >>= 1) s += __shfl_xor_sync(0xffffffffu, s, o);
    if ((tid & 31) == 0) rsum[tid >> 5] = s;
    __syncthreads();
    s = 0.f;
#pragma unroll
    for (int i = 0; i < 8; i++) s += rsum[i];
    float inv = 1.f / s;
    va.x = v[0] * inv; va.y = v[1] * inv; va.z = v[2] * inv; va.w = v[3] * inv;
    vb.x = v[4] * inv; vb.y = v[5] * inv; vb.z = v[6] * inv; vb.w = v[7] * inv;
    p[tid] = va; p[tid + 256] = vb;
}

__global__ void __launch_bounds__(256) ln_relu_k(
    float* __restrict__ h, const float* __restrict__ g, const float* __restrict__ b)
{
    float* p = h + (size_t)blockIdx.x * Cc;
    const int tid = threadIdx.x;
    float v[4];
    float s = 0.f, ss = 0.f;
#pragma unroll
    for (int i = 0; i < 4; i++) {
        v[i] = p[tid + 256 * i];
        s += v[i];
        ss += v[i] * v[i];
    }
#pragma unroll
    for (int o = 16; o; o >>= 1) {
        s  += __shfl_xor_sync(0xffffffffu, s, o);
        ss += __shfl_xor_sync(0xffffffffu, ss, o);
    }
    __shared__ float r1[8], r2[8];
    if ((tid & 31) == 0) { r1[tid >> 5] = s; r2[tid >> 5] = ss; }
    __syncthreads();
    s = 0.f; ss = 0.f;
#pragma unroll
    for (int i = 0; i < 8; i++) { s += r1[i]; ss += r2[i]; }
    float mean = s * (1.f / Cc);
    float var  = ss * (1.f / Cc) - mean * mean;
    float inv  = rsqrtf(var + 1e-5f);
#pragma unroll
    for (int i = 0; i < 4; i++) {
        int c = tid + 256 * i;
        float y = (v[i] - mean) * inv * g[c] + b[c];
        p[c] = fmaxf(y, 0.f);
    }
}

// ---------------------------------------------------------------------------
extern "C" void kernel_launch(void* const* d_in, const int* in_sizes, int n_in,
                              void* d_out, int out_size)
{
    (void)in_sizes; (void)n_in; (void)out_size;
    const float* x       = (const float*)d_in[0];
    const float* lfb     = (const float*)d_in[1];
    const float* theta_w = (const float*)d_in[2];
    const float* theta_b = (const float*)d_in[3];
    const float* phi_w   = (const float*)d_in[4];
    const float* phi_b   = (const float*)d_in[5];
    const float* gi_w    = (const float*)d_in[6];
    const float* gi_b    = (const float*)d_in[7];
    const float* ln_g    = (const float*)d_in[8];
    const float* ln_b    = (const float*)d_in[9];
    const float* fc_w    = (const float*)d_in[10];
    const float* fc_b    = (const float*)d_in[11];
    float* out = (float*)d_out;

    float *P, *giT, *logits, *att, *twT, *pwT, *Mt, *vp, *v, *cb;
    cudaGetSymbolAddress((void**)&P,      g_P);
    cudaGetSymbolAddress((void**)&giT,    g_giT);
    cudaGetSymbolAddress((void**)&logits, g_logits);
    cudaGetSymbolAddress((void**)&att,    g_att);
    cudaGetSymbolAddress((void**)&twT,    g_twT);
    cudaGetSymbolAddress((void**)&pwT,    g_pwT);
    cudaGetSymbolAddress((void**)&Mt,     g_Mt);
    cudaGetSymbolAddress((void**)&vp,     g_vp);
    cudaGetSymbolAddress((void**)&v,      g_v);
    cudaGetSymbolAddress((void**)&cb,     g_cb);

    // one-time resources (no device memory; same launches every call)
    static bool s_init = false;
    static cudaStream_t s1, s2;
    static cudaEvent_t ev0, evG, evC;
    if (!s_init) {
        cudaStreamCreateWithFlags(&s1, cudaStreamNonBlocking);
        cudaStreamCreateWithFlags(&s2, cudaStreamNonBlocking);
        cudaEventCreateWithFlags(&ev0, cudaEventDisableTiming);
        cudaEventCreateWithFlags(&evG, cudaEventDisableTiming);
        cudaEventCreateWithFlags(&evC, cudaEventDisableTiming);
        s_init = true;
    }

    cudaFuncSetAttribute(gemm_cp<true,  false>,
        cudaFuncAttributeMaxDynamicSharedMemorySize, SMEM_ALL);
    cudaFuncSetAttribute(gemm_cp<false, false>,
        cudaFuncAttributeMaxDynamicSharedMemorySize, SMEM_ALL);
    cudaFuncSetAttribute(gemm_cp<false, true>,
        cudaFuncAttributeMaxDynamicSharedMemorySize, SMEM_ALL);

    dim3 blk(256);

    // fork side streams off the origin stream
    cudaEventRecord(ev0, 0);
    cudaStreamWaitEvent(s1, ev0, 0);
    cudaStreamWaitEvent(s2, ev0, 0);

    // s1: giT[b][c][s] = (lfb @ gi_w^T + gi_b)^T   (independent until AV)
    gemm_cp<false, true><<<dim3(8, 128, 1), blk, SMEM_ALL, s1>>>(
        lfb, gi_w, gi_b, nullptr, giT, Cc, Cc, 1.f, 0, 0, 0, 0);
    cudaEventRecord(evG, s1);

    // s2: v = phi_w^T theta_b ; cb = 32*(lfb.v)    (needed by logits)
    vker_part<<<dim3(4, 32), blk, 0, s2>>>(theta_b, phi_w, vp);
    vker_red<<<4, blk, 0, s2>>>(vp, v);
    cbias_k<<<Bv * Ss / 8, blk, 0, s2>>>(lfb, v, cb);
    cudaEventRecord(evC, s2);

    // origin: transposes -> Mt -> P
    transpose_k<<<dim3(32, 32), dim3(32, 8)>>>(theta_w, twT);
    transpose_k<<<dim3(32, 32), dim3(32, 8)>>>(phi_w, pwT);
    gemm_cp<true, false><<<dim3(8, 8, 1), blk, SMEM_ALL>>>(
        pwT, twT, nullptr, nullptr, Mt, Cc, Cc, 1.f, 0, 0, 0, 0);
    gemm_cp<true, false><<<dim3(8, 64, 1), blk, SMEM_ALL>>>(
        x, Mt, nullptr, nullptr, P, Cc, Cc, 1.f, 0, 0, 0, 0);

    // join cb, then logits + softmax
    cudaStreamWaitEvent(0, evC, 0);
    gemm_cp<true, false><<<dim3(16, 8, Bv), blk, SMEM_ALL>>>(
        P, lfb, cb, nullptr, logits, Ss, Cc, 32.f,
        (size_t)Tt * Cc, (size_t)Ss * Cc, (size_t)Tt * Ss, (size_t)Ss);
    softmax_k<<<Bv * Tt, blk>>>(logits);

    // join giT, then AV -> LN -> fc
    cudaStreamWaitEvent(0, evG, 0);
    gemm_cp<false, false><<<dim3(8, 8, Bv), blk, SMEM_ALL>>>(
        logits, giT, nullptr, nullptr, att, Cc, Ss, 1.f,
        (size_t)Tt * Ss, (size_t)Cc * Ss, (size_t)Tt * Cc, 0);
    ln_relu_k<<<Bv * Tt, blk>>>(att, ln_g, ln_b);
    gemm_cp<false, false><<<dim3(8, 64, 1), blk, SMEM_ALL>>>(
        att, fc_w, fc_b, x, out, Cc, Cc, 1.f, 0, 0, 0, 0);
}